// round 5
// baseline (speedup 1.0000x reference)
#include <cuda_runtime.h>
#include <cuda_bf16.h>

// ---------------------------------------------------------------------------
// NSA forward. R4: cp.async double-buffered tensor-core GEMMs (split-bf16,
// 3-term), fused+vectorized slc/win attention, fused elementwise launches.
// ---------------------------------------------------------------------------

namespace {
constexpr int S_ = 1024;
constexpr int D_ = 2048;
constexpr int H_ = 32;
constexpr int G_ = 2;
constexpr int HG_ = 16;
constexpr int DQ_ = 128;
constexpr int DV_ = 128;
constexpr int BLK_ = 64;
constexpr int C_ = 16;
constexpr int TOPN_ = 4;
constexpr int WIN_ = 256;
constexpr int NQ_ = H_ * DQ_;   // 4096
constexpr int NKV_ = G_ * DQ_;  // 256
constexpr int NC_ = H_ * 3;     // 96
constexpr float SCALE_ = 0.08838834764831845f;
}

// fp32 scratch
__device__ float g_qraw[S_ * NQ_];
__device__ float g_q[S_ * NQ_];
__device__ float g_kraw[S_ * NKV_];
__device__ float g_k[S_ * NKV_];
__device__ float g_v[S_ * NKV_];
__device__ float g_gates[S_ * NC_];
__device__ float g_kc[C_ * G_ * DQ_];
__device__ float g_vc[C_ * G_ * DV_];
__device__ int   g_idx[S_ * G_ * TOPN_];
__device__ float g_ocomb[S_ * H_ * DV_];

// bf16 split planes
__device__ __align__(16) __nv_bfloat16 g_xh[S_ * D_],  g_xl[S_ * D_];
__device__ __align__(16) __nv_bfloat16 g_Wqh[D_ * NQ_], g_Wql[D_ * NQ_];
__device__ __align__(16) __nv_bfloat16 g_Wkh[D_ * NKV_], g_Wkl[D_ * NKV_];
__device__ __align__(16) __nv_bfloat16 g_Wvh[D_ * NKV_], g_Wvl[D_ * NKV_];
__device__ __align__(16) __nv_bfloat16 g_Wch[D_ * NC_],  g_Wcl[D_ * NC_];
__device__ __align__(16) __nv_bfloat16 g_Woh[H_ * DV_ * D_], g_Wol[H_ * DV_ * D_];
__device__ __align__(16) __nv_bfloat16 g_oh[S_ * H_ * DV_], g_ol[S_ * H_ * DV_];

__device__ __forceinline__ float warp_sum(float v) {
#pragma unroll
    for (int o = 16; o > 0; o >>= 1) v += __shfl_xor_sync(0xffffffffu, v, o);
    return v;
}
__device__ __forceinline__ float warp_max(float v) {
#pragma unroll
    for (int o = 16; o > 0; o >>= 1) v = fmaxf(v, __shfl_xor_sync(0xffffffffu, v, o));
    return v;
}

// ---- tensor-core / async primitives ---------------------------------------
__device__ __forceinline__ void ldsm_x4(unsigned (&r)[4], unsigned saddr) {
    asm volatile("ldmatrix.sync.aligned.m8n8.x4.shared.b16 {%0,%1,%2,%3}, [%4];"
                 : "=r"(r[0]), "=r"(r[1]), "=r"(r[2]), "=r"(r[3]) : "r"(saddr));
}
__device__ __forceinline__ void ldsm_x4_t(unsigned (&r)[4], unsigned saddr) {
    asm volatile("ldmatrix.sync.aligned.m8n8.x4.trans.shared.b16 {%0,%1,%2,%3}, [%4];"
                 : "=r"(r[0]), "=r"(r[1]), "=r"(r[2]), "=r"(r[3]) : "r"(saddr));
}
__device__ __forceinline__ void mma_bf16(float (&c)[4], const unsigned (&a)[4],
                                         unsigned b0, unsigned b1) {
    asm volatile(
        "mma.sync.aligned.m16n8k16.row.col.f32.bf16.bf16.f32 "
        "{%0,%1,%2,%3}, {%4,%5,%6,%7}, {%8,%9}, {%0,%1,%2,%3};"
        : "+f"(c[0]), "+f"(c[1]), "+f"(c[2]), "+f"(c[3])
        : "r"(a[0]), "r"(a[1]), "r"(a[2]), "r"(a[3]), "r"(b0), "r"(b1));
}
__device__ __forceinline__ void cp16(unsigned dst, const void* src, bool valid) {
    int sz = valid ? 16 : 0;
    asm volatile("cp.async.cg.shared.global [%0], [%1], 16, %2;"
                 :: "r"(dst), "l"(src), "r"(sz));
}
#define CP_COMMIT() asm volatile("cp.async.commit_group;")
#define CP_WAIT(n) asm volatile("cp.async.wait_group %0;" :: "n"(n))

// ---------------------------------------------------------------------------
// Fused split-convert: one kernel handles all 6 fp32 -> (bf16 hi, bf16 lo)
// ---------------------------------------------------------------------------
__global__ __launch_bounds__(256) void cvt_all_kernel(
    const float* __restrict__ x, const float* __restrict__ Wq,
    const float* __restrict__ Wk, const float* __restrict__ Wv,
    const float* __restrict__ Wc, const float* __restrict__ Wo) {
    // n4 prefix (float4 units)
    // x: 524288 | Wq: 2097152 | Wk: 131072 | Wv: 131072 | Wc: 49152 | Wo: 2097152
    long long i = (long long)blockIdx.x * 256 + threadIdx.x;
    const float* src;
    __nv_bfloat16 *hi, *lo;
    long long off;
    if (i < 524288)            { src = x;  hi = g_xh;  lo = g_xl;  off = i; }
    else if (i < 2621440)      { src = Wq; hi = g_Wqh; lo = g_Wql; off = i - 524288; }
    else if (i < 2752512)      { src = Wk; hi = g_Wkh; lo = g_Wkl; off = i - 2621440; }
    else if (i < 2883584)      { src = Wv; hi = g_Wvh; lo = g_Wvl; off = i - 2752512; }
    else if (i < 2932736)      { src = Wc; hi = g_Wch; lo = g_Wcl; off = i - 2883584; }
    else if (i < 5029888)      { src = Wo; hi = g_Woh; lo = g_Wol; off = i - 2932736; }
    else return;
    float4 v = ((const float4*)src)[off];
    __nv_bfloat16 h0 = __float2bfloat16(v.x), h1 = __float2bfloat16(v.y);
    __nv_bfloat16 h2 = __float2bfloat16(v.z), h3 = __float2bfloat16(v.w);
    __nv_bfloat162 a, b;
    a.x = h0; a.y = h1; b.x = h2; b.y = h3;
    ((__nv_bfloat162*)hi)[off * 2] = a;
    ((__nv_bfloat162*)hi)[off * 2 + 1] = b;
    a.x = __float2bfloat16(v.x - __bfloat162float(h0));
    a.y = __float2bfloat16(v.y - __bfloat162float(h1));
    b.x = __float2bfloat16(v.z - __bfloat162float(h2));
    b.y = __float2bfloat16(v.w - __bfloat162float(h3));
    ((__nv_bfloat162*)lo)[off * 2] = a;
    ((__nv_bfloat162*)lo)[off * 2 + 1] = b;
}

__global__ __launch_bounds__(256) void cvt_ocomb_kernel() {
    int i = blockIdx.x * 256 + threadIdx.x;
    if (i >= S_ * H_ * DV_ / 4) return;
    float4 v = ((const float4*)g_ocomb)[i];
    __nv_bfloat16 h0 = __float2bfloat16(v.x), h1 = __float2bfloat16(v.y);
    __nv_bfloat16 h2 = __float2bfloat16(v.z), h3 = __float2bfloat16(v.w);
    __nv_bfloat162 a, b;
    a.x = h0; a.y = h1; b.x = h2; b.y = h3;
    ((__nv_bfloat162*)g_oh)[i * 2] = a;
    ((__nv_bfloat162*)g_oh)[i * 2 + 1] = b;
    a.x = __float2bfloat16(v.x - __bfloat162float(h0));
    a.y = __float2bfloat16(v.y - __bfloat162float(h1));
    b.x = __float2bfloat16(v.z - __bfloat162float(h2));
    b.y = __float2bfloat16(v.w - __bfloat162float(h3));
    ((__nv_bfloat162*)g_ol)[i * 2] = a;
    ((__nv_bfloat162*)g_ol)[i * 2 + 1] = b;
}

// ---------------------------------------------------------------------------
// cp.async double-buffered MMA GEMM. 128x128 tile, K-step 32, 8 warps.
// Smem per stage: Ah(8K swizzled 64B rows) Al(8K) Bh(8.5K) Bl(8.5K) = 33792B.
// ---------------------------------------------------------------------------
namespace {
constexpr unsigned OFF_AL = 8192;
constexpr unsigned OFF_BH = 16384;
constexpr unsigned OFF_BL = 25088;
constexpr unsigned STAGE_BYTES = 33792;
}
__device__ __forceinline__ unsigned swA(int r, int c) {
    return (unsigned)(r * 64) + ((unsigned)(c ^ ((r >> 1) & 3)) << 4);
}

__device__ __forceinline__ void gemm_tile_async(
    const __nv_bfloat16* __restrict__ Agh, const __nv_bfloat16* __restrict__ Agl,
    int lda,
    const __nv_bfloat16* __restrict__ Bgh, const __nv_bfloat16* __restrict__ Bgl,
    int ldb,
    float* __restrict__ Cp, int ldc,
    int K, int Nloc, int bm, int bn, char* dynsm) {
    const int tid = threadIdx.x;
    const int lane = tid & 31;
    const int w = tid >> 5;
    const int wm = (w >> 1) * 32;
    const int wn = (w & 1) * 64;

    const int ar0 = tid >> 2, ac0 = tid & 3;   // A rows 0..63, chunk 0..3 (16B)
    const int ar1 = ar0 + 64;
    const int br0 = tid >> 4, bc0 = tid & 15;  // B rows 0..15, chunk 0..15 (16B)
    const int br1 = br0 + 16;
    const bool bok = (bn + bc0 * 8 + 7) < Nloc;

    const unsigned sbase = (unsigned)__cvta_generic_to_shared(dynsm);

    float c[2][8][4];
#pragma unroll
    for (int i = 0; i < 2; i++)
#pragma unroll
        for (int j = 0; j < 8; j++)
#pragma unroll
            for (int q = 0; q < 4; q++) c[i][j][q] = 0.f;

    auto issue = [&](int step, int stage) {
        const unsigned base = sbase + stage * STAGE_BYTES;
        const int k0 = step * 32;
        cp16(base + swA(ar0, ac0), Agh + (size_t)(bm + ar0) * lda + k0 + ac0 * 8, true);
        cp16(base + swA(ar1, ac0), Agh + (size_t)(bm + ar1) * lda + k0 + ac0 * 8, true);
        cp16(base + OFF_AL + swA(ar0, ac0), Agl + (size_t)(bm + ar0) * lda + k0 + ac0 * 8, true);
        cp16(base + OFF_AL + swA(ar1, ac0), Agl + (size_t)(bm + ar1) * lda + k0 + ac0 * 8, true);
        const __nv_bfloat16* b0 = bok ? Bgh + (size_t)(k0 + br0) * ldb + bn + bc0 * 8 : Bgh;
        const __nv_bfloat16* b1 = bok ? Bgh + (size_t)(k0 + br1) * ldb + bn + bc0 * 8 : Bgh;
        const __nv_bfloat16* b2 = bok ? Bgl + (size_t)(k0 + br0) * ldb + bn + bc0 * 8 : Bgl;
        const __nv_bfloat16* b3 = bok ? Bgl + (size_t)(k0 + br1) * ldb + bn + bc0 * 8 : Bgl;
        cp16(base + OFF_BH + br0 * 272 + bc0 * 16, b0, bok);
        cp16(base + OFF_BH + br1 * 272 + bc0 * 16, b1, bok);
        cp16(base + OFF_BL + br0 * 272 + bc0 * 16, b2, bok);
        cp16(base + OFF_BL + br1 * 272 + bc0 * 16, b3, bok);
    };

    const int nSteps = K >> 5;
    issue(0, 0);
    CP_COMMIT();

    for (int step = 0; step < nSteps; step++) {
        const int cur = step & 1;
        if (step + 1 < nSteps) {
            issue(step + 1, cur ^ 1);
            CP_COMMIT();
            CP_WAIT(1);
        } else {
            CP_WAIT(0);
        }
        __syncthreads();

        const unsigned base = sbase + cur * STAGE_BYTES;
#pragma unroll
        for (int kk = 0; kk < 2; kk++) {
            unsigned ah[2][4], al[2][4], bh[4][4], bl[4][4];
#pragma unroll
            for (int i = 0; i < 2; i++) {
                int arow = wm + 16 * i + (lane & 15);
                int achunk = kk * 2 + (lane >> 4);
                unsigned off = swA(arow, achunk);
                ldsm_x4(ah[i], base + off);
                ldsm_x4(al[i], base + OFF_AL + off);
            }
#pragma unroll
            for (int j = 0; j < 4; j++) {
                unsigned brow = kk * 16 + (lane & 15);
                unsigned bcol = wn + 16 * j + 8 * (lane >> 4);
                unsigned off = brow * 272 + bcol * 2;
                ldsm_x4_t(bh[j], base + OFF_BH + off);
                ldsm_x4_t(bl[j], base + OFF_BL + off);
            }
#pragma unroll
            for (int i = 0; i < 2; i++) {
#pragma unroll
                for (int jn = 0; jn < 8; jn++) {
                    const int j = jn >> 1, p = (jn & 1) * 2;
                    mma_bf16(c[i][jn], ah[i], bh[j][p], bh[j][p + 1]);
                    mma_bf16(c[i][jn], ah[i], bl[j][p], bl[j][p + 1]);
                    mma_bf16(c[i][jn], al[i], bh[j][p], bh[j][p + 1]);
                }
            }
        }
        __syncthreads();
    }

    const int qrow = lane >> 2;
    const int qcol = (lane & 3) * 2;
#pragma unroll
    for (int i = 0; i < 2; i++) {
        const int row0 = bm + wm + 16 * i + qrow;
#pragma unroll
        for (int jn = 0; jn < 8; jn++) {
            const int col = bn + wn + jn * 8 + qcol;
            if (col < Nloc) {
                *(float2*)&Cp[(size_t)row0 * ldc + col] =
                    make_float2(c[i][jn][0], c[i][jn][1]);
                *(float2*)&Cp[(size_t)(row0 + 8) * ldc + col] =
                    make_float2(c[i][jn][2], c[i][jn][3]);
            }
        }
    }
}

__global__ __launch_bounds__(256) void fused_proj_mma(
    float* __restrict__ qraw, float* __restrict__ kraw,
    float* __restrict__ v, float* __restrict__ gates) {
    extern __shared__ char dynsm[];
    const int t = blockIdx.x;
    const int bm = blockIdx.y * 128;
    const __nv_bfloat16 *Bh, *Bl;
    float* Cp;
    int Nloc, bn;
    if (t < 32)      { Bh = g_Wqh; Bl = g_Wql; Cp = qraw;  Nloc = NQ_;  bn = t * 128; }
    else if (t < 34) { Bh = g_Wkh; Bl = g_Wkl; Cp = kraw;  Nloc = NKV_; bn = (t - 32) * 128; }
    else if (t < 36) { Bh = g_Wvh; Bl = g_Wvl; Cp = v;     Nloc = NKV_; bn = (t - 34) * 128; }
    else             { Bh = g_Wch; Bl = g_Wcl; Cp = gates; Nloc = NC_;  bn = 0; }
    gemm_tile_async(g_xh, g_xl, D_, Bh, Bl, Nloc, Cp, Nloc, D_, Nloc, bm, bn, dynsm);
}

__global__ __launch_bounds__(256) void gemm_out_mma(float* __restrict__ out) {
    extern __shared__ char dynsm[];
    gemm_tile_async(g_oh, g_ol, H_ * DV_, g_Woh, g_Wol, D_, out, D_,
                    H_ * DV_, D_, blockIdx.y * 128, blockIdx.x * 128, dynsm);
}

// ---------------------------------------------------------------------------
// Fused elementwise: RoPE(q), RoPE(k), sigmoid(gates) via flat routing.
// ---------------------------------------------------------------------------
__global__ __launch_bounds__(256) void ew_all_kernel(const float* __restrict__ cosp,
                                                     const float* __restrict__ sinp) {
    int i = blockIdx.x * 256 + threadIdx.x;
    if (i < S_ * NQ_) {  // rope q: 4194304
        int d = i & 127;
        int s = i >> 12;
        float c = cosp[s * DQ_ + d], sn = sinp[s * DQ_ + d];
        float t = g_qraw[i];
        float rot = (d < 64) ? -g_qraw[i + 64] : g_qraw[i - 64];
        g_q[i] = t * c + rot * sn;
        return;
    }
    i -= S_ * NQ_;
    if (i < S_ * NKV_) {  // rope k: 262144
        int d = i & 127;
        int s = i >> 8;
        float c = cosp[s * DQ_ + d], sn = sinp[s * DQ_ + d];
        float t = g_kraw[i];
        float rot = (d < 64) ? -g_kraw[i + 64] : g_kraw[i - 64];
        g_k[i] = t * c + rot * sn;
        return;
    }
    i -= S_ * NKV_;
    if (i < S_ * NC_) {  // sigmoid: 98304
        g_gates[i] = 1.f / (1.f + expf(-g_gates[i]));
    }
}

__global__ __launch_bounds__(256) void kcvc_kernel() {
    int i = blockIdx.x * 256 + threadIdx.x;
    if (i >= C_ * G_ * DQ_) return;
    int d = i & 127;
    int g = (i >> 7) & 1;
    int c = i >> 8;
    float sk = 0.f, sv = 0.f;
    for (int j = 0; j < BLK_; j++) {
        int t = c * BLK_ + j;
        sk += g_k[(t * G_ + g) * DQ_ + d];
        sv += g_v[(t * G_ + g) * DV_ + d];
    }
    g_kc[i] = sk * (1.f / 64.f);
    g_vc[i] = sv * (1.f / 64.f);
}

// ---------------------------------------------------------------------------
// Compressed attention + importance + stable top-4 selection (unchanged).
// ---------------------------------------------------------------------------
__global__ __launch_bounds__(512) void cmp_attn_kernel() {
    const int s = blockIdx.x;
    const int g = blockIdx.y;
    __shared__ float kcs[C_][DQ_];
    __shared__ float vcs[C_][DQ_];
    __shared__ float pw[HG_][C_];
    const int tid = threadIdx.x;

    for (int i = tid; i < C_ * DQ_; i += 512) {
        int c = i >> 7, d = i & 127;
        kcs[c][d] = g_kc[(c * G_ + g) * DQ_ + d];
        vcs[c][d] = g_vc[(c * G_ + g) * DV_ + d];
    }
    __syncthreads();

    const int w = tid >> 5, l = tid & 31;
    const int h = g * HG_ + w;
    const float* qp = &g_q[(s * H_ + h) * DQ_];
    float q0 = qp[l], q1 = qp[l + 32], q2 = qp[l + 64], q3 = qp[l + 96];

    const int ncmp = (s + 1) >> 6;
    float logit[C_];
#pragma unroll
    for (int c = 0; c < C_; c++) {
        if (c < ncmp) {
            float part = q0 * kcs[c][l] + q1 * kcs[c][l + 32] +
                         q2 * kcs[c][l + 64] + q3 * kcs[c][l + 96];
            logit[c] = warp_sum(part) * SCALE_;
        } else {
            logit[c] = -1e30f;
        }
    }
    float m = -1e30f;
#pragma unroll
    for (int c = 0; c < C_; c++) m = fmaxf(m, logit[c]);
    float p[C_];
    float sum = 0.f;
#pragma unroll
    for (int c = 0; c < C_; c++) {
        float e = (logit[c] > -1e29f) ? expf(logit[c] - m) : 0.f;
        p[c] = e;
        sum += e;
    }
    float inv = (sum > 0.f) ? 1.f / sum : 0.f;

    float o0 = 0.f, o1 = 0.f, o2 = 0.f, o3 = 0.f;
#pragma unroll
    for (int c = 0; c < C_; c++) {
        float pc = p[c] * inv;
        o0 += pc * vcs[c][l];
        o1 += pc * vcs[c][l + 32];
        o2 += pc * vcs[c][l + 64];
        o3 += pc * vcs[c][l + 96];
        if (l == 0) pw[w][c] = pc;
    }
    float gate = g_gates[(s * H_ + h) * 3 + 0];
    float* op = &g_ocomb[(s * H_ + h) * DV_];
    op[l]      = gate * o0;
    op[l + 32] = gate * o1;
    op[l + 64] = gate * o2;
    op[l + 96] = gate * o3;
    __syncthreads();

    if (tid == 0) {
        const int cur = s >> 6;
        float imp[C_];
        for (int c = 0; c < C_; c++) {
            float v;
            if (c > cur) v = -1e9f;
            else if (c == 0 || c == cur) v = 1e9f;
            else {
                v = 0.f;
                for (int ww = 0; ww < HG_; ww++) v += pw[ww][c];
            }
            imp[c] = v;
        }
        bool tk[C_];
        for (int c = 0; c < C_; c++) tk[c] = false;
        for (int t = 0; t < TOPN_; t++) {
            float best = -3e38f;
            int bi = 0;
            for (int c = 0; c < C_; c++)
                if (!tk[c] && imp[c] > best) { best = imp[c]; bi = c; }
            tk[bi] = true;
            g_idx[(s * G_ + g) * TOPN_ + t] = bi;
        }
    }
}

// ---------------------------------------------------------------------------
// Fused selected + window attention. One CTA per (s, g), 16 warps = heads.
// K staged key-major [64][132] (float4 reads, conflict-free); V staged
// dim-major [128][68]. Single gated RMW on g_ocomb for both branches.
// ---------------------------------------------------------------------------
struct SlcWinSmem {
    union {
        float k[BLK_][132];   // key-major, QK phase
        float v[DV_][68];     // dim-major, PV phase
    } kv;
    float qsh[HG_][DQ_];
    int idxs[TOPN_];
};

__device__ __forceinline__ void stage_k(SlcWinSmem& sm, int t0, int g, int tid) {
    for (int i = tid; i < BLK_ * 32; i += 512) {
        int j = i >> 5, d4 = i & 31;
        float4 v = *(const float4*)&g_k[((t0 + j) * G_ + g) * DQ_ + d4 * 4];
        *(float4*)&sm.kv.k[j][d4 * 4] = v;
    }
}
__device__ __forceinline__ void stage_v(SlcWinSmem& sm, int t0, int g, int tid) {
    for (int i = tid; i < BLK_ * 32; i += 512) {
        int j = i >> 5, d4 = i & 31;
        float4 v = *(const float4*)&g_v[((t0 + j) * G_ + g) * DV_ + d4 * 4];
        sm.kv.v[d4 * 4 + 0][j] = v.x;
        sm.kv.v[d4 * 4 + 1][j] = v.y;
        sm.kv.v[d4 * 4 + 2][j] = v.z;
        sm.kv.v[d4 * 4 + 3][j] = v.w;
    }
}

// QK for one staged block: lane computes logits for keys l and l+32.
__device__ __forceinline__ void qk_block(const SlcWinSmem& sm, int w, int l,
                                         float& a0, float& a1) {
    a0 = 0.f; a1 = 0.f;
#pragma unroll
    for (int d4 = 0; d4 < 32; d4++) {
        float4 qv = *(const float4*)&sm.qsh[w][d4 * 4];
        float4 k0 = *(const float4*)&sm.kv.k[l][d4 * 4];
        float4 k1 = *(const float4*)&sm.kv.k[l + 32][d4 * 4];
        a0 += qv.x * k0.x + qv.y * k0.y + qv.z * k0.z + qv.w * k0.w;
        a1 += qv.x * k1.x + qv.y * k1.y + qv.z * k1.z + qv.w * k1.w;
    }
}

// PV for one staged block: accumulate 4 output dims (l, l+32, l+64, l+96).
__device__ __forceinline__ void pv_block(const SlcWinSmem& sm, int l,
                                         float p0reg, float p1reg,
                                         float& o0, float& o1, float& o2, float& o3) {
#pragma unroll
    for (int j4 = 0; j4 < 16; j4++) {
        float preg = (j4 < 8) ? p0reg : p1reg;
        int base = (4 * j4) & 31;
        float p0 = __shfl_sync(0xffffffffu, preg, base + 0);
        float p1 = __shfl_sync(0xffffffffu, preg, base + 1);
        float p2 = __shfl_sync(0xffffffffu, preg, base + 2);
        float p3 = __shfl_sync(0xffffffffu, preg, base + 3);
        float4 v0 = *(const float4*)&sm.kv.v[l][j4 * 4];
        float4 v1 = *(const float4*)&sm.kv.v[l + 32][j4 * 4];
        float4 v2 = *(const float4*)&sm.kv.v[l + 64][j4 * 4];
        float4 v3 = *(const float4*)&sm.kv.v[l + 96][j4 * 4];
        o0 += p0 * v0.x + p1 * v0.y + p2 * v0.z + p3 * v0.w;
        o1 += p0 * v1.x + p1 * v1.y + p2 * v1.z + p3 * v1.w;
        o2 += p0 * v2.x + p1 * v2.y + p2 * v2.z + p3 * v2.w;
        o3 += p0 * v3.x + p1 * v3.y + p2 * v3.z + p3 * v3.w;
    }
}

__global__ __launch_bounds__(512) void slcwin_attn_kernel() {
    const int s = blockIdx.x, g = blockIdx.y;
    __shared__ SlcWinSmem sm;
    const int tid = threadIdx.x;
    const int w = tid >> 5, l = tid & 31;

    for (int i = tid; i < HG_ * DQ_; i += 512)
        sm.qsh[i >> 7][i & 127] = g_q[(s * H_ + g * HG_ + (i >> 7)) * DQ_ + (i & 127)];
    if (tid < TOPN_) sm.idxs[tid] = g_idx[(s * G_ + g) * TOPN_ + tid];
    __syncthreads();

    int blk[TOPN_];
#pragma unroll
    for (int n = 0; n < TOPN_; n++) blk[n] = sm.idxs[n];

    float ls[8];
    float oS0 = 0.f, oS1 = 0.f, oS2 = 0.f, oS3 = 0.f;

    // ---------------- selected branch ----------------
#pragma unroll
    for (int n = 0; n < TOPN_; n++) {
        const int t0 = blk[n] * BLK_;
        stage_k(sm, t0, g, tid);
        __syncthreads();
        float a0, a1;
        qk_block(sm, w, l, a0, a1);
        ls[n * 2 + 0] = (t0 + l <= s) ? a0 * SCALE_ : -1e30f;
        ls[n * 2 + 1] = (t0 + l + 32 <= s) ? a1 * SCALE_ : -1e30f;
        __syncthreads();
    }
    {
        float m = -1e30f;
#pragma unroll
        for (int r = 0; r < 8; r++) m = fmaxf(m, ls[r]);
        m = warp_max(m);
        float sum = 0.f;
#pragma unroll
        for (int r = 0; r < 8; r++) {
            ls[r] = (ls[r] > -1e29f) ? expf(ls[r] - m) : 0.f;
            sum += ls[r];
        }
        sum = warp_sum(sum);
        float inv = 1.f / sum;
#pragma unroll
        for (int r = 0; r < 8; r++) ls[r] *= inv;
    }
#pragma unroll
    for (int n = 0; n < TOPN_; n++) {
        stage_v(sm, blk[n] * BLK_, g, tid);
        __syncthreads();
        pv_block(sm, l, ls[n * 2], ls[n * 2 + 1], oS0, oS1, oS2, oS3);
        __syncthreads();
    }

    // ---------------- window branch ----------------
    const int wstart = (s >= WIN_) ? (s - WIN_ + 1) : 0;
    float oW0 = 0.f, oW1 = 0.f, oW2 = 0.f, oW3 = 0.f;
#pragma unroll
    for (int n = 0; n < 4; n++) {
        const int t0 = wstart + n * BLK_;
        stage_k(sm, t0, g, tid);
        __syncthreads();
        float a0, a1;
        qk_block(sm, w, l, a0, a1);
        ls[n * 2 + 0] = (t0 + l <= s) ? a0 * SCALE_ : -1e30f;
        ls[n * 2 + 1] = (t0 + l + 32 <= s) ? a1 * SCALE_ : -1e30f;
        __syncthreads();
    }
    {
        float m = -1e30f;
#pragma unroll
        for (int r = 0; r < 8; r++) m = fmaxf(m, ls[r]);
        m = warp_max(m);
        float sum = 0.f;
#pragma unroll
        for (int r = 0; r < 8; r++) {
            ls[r] = (ls[r] > -1e29f) ? expf(ls[r] - m) : 0.f;
            sum += ls[r];
        }
        sum = warp_sum(sum);
        float inv = 1.f / sum;
#pragma unroll
        for (int r = 0; r < 8; r++) ls[r] *= inv;
    }
#pragma unroll
    for (int n = 0; n < 4; n++) {
        stage_v(sm, wstart + n * BLK_, g, tid);
        __syncthreads();
        pv_block(sm, l, ls[n * 2], ls[n * 2 + 1], oW0, oW1, oW2, oW3);
        __syncthreads();
    }

    // single RMW combine
    const int h = g * HG_ + w;
    float g1 = g_gates[(s * H_ + h) * 3 + 1];
    float g2 = g_gates[(s * H_ + h) * 3 + 2];
    float* op = &g_ocomb[(s * H_ + h) * DV_];
    op[l]      += g1 * oS0 + g2 * oW0;
    op[l + 32] += g1 * oS1 + g2 * oW1;
    op[l + 64] += g1 * oS2 + g2 * oW2;
    op[l + 96] += g1 * oS3 + g2 * oW3;
}

// ---------------------------------------------------------------------------
extern "C" void kernel_launch(void* const* d_in, const int* in_sizes, int n_in,
                              void* d_out, int out_size) {
    const float* x    = (const float*)d_in[0];
    const float* cosp = (const float*)d_in[1];
    const float* sinp = (const float*)d_in[2];
    const float* Wq   = (const float*)d_in[3];
    const float* Wk   = (const float*)d_in[4];
    const float* Wv   = (const float*)d_in[5];
    const float* Wo   = (const float*)d_in[6];
    const float* Wc   = (const float*)d_in[7];
    float* out = (float*)d_out;

    float *p_qraw, *p_kraw, *p_v, *p_gates;
    cudaGetSymbolAddress((void**)&p_qraw, g_qraw);
    cudaGetSymbolAddress((void**)&p_kraw, g_kraw);
    cudaGetSymbolAddress((void**)&p_v, g_v);
    cudaGetSymbolAddress((void**)&p_gates, g_gates);

    const unsigned gemm_smem = 2 * STAGE_BYTES;  // 67584
    static bool attr_done = false;
    if (!attr_done) {
        cudaFuncSetAttribute(fused_proj_mma,
                             cudaFuncAttributeMaxDynamicSharedMemorySize, gemm_smem);
        cudaFuncSetAttribute(gemm_out_mma,
                             cudaFuncAttributeMaxDynamicSharedMemorySize, gemm_smem);
        attr_done = true;
    }

    // split conversions (one launch)
    cvt_all_kernel<<<(5029888 + 255) / 256, 256>>>(x, Wq, Wk, Wv, Wc, Wo);

    // fused projections: 37 n-tiles x 8 m-tiles
    fused_proj_mma<<<dim3(37, 8), 256, gemm_smem>>>(p_qraw, p_kraw, p_v, p_gates);

    // fused elementwise (rope q, rope k, sigmoid) + block means
    ew_all_kernel<<<(S_ * NQ_ + S_ * NKV_ + S_ * NC_ + 255) / 256, 256>>>(cosp, sinp);
    kcvc_kernel<<<(C_ * G_ * DQ_ + 255) / 256, 256>>>();

    // attention
    cmp_attn_kernel<<<dim3(S_, G_), 512>>>();
    slcwin_attn_kernel<<<dim3(S_, G_), 512>>>();

    // split ocomb, output projection
    cvt_ocomb_kernel<<<(S_ * H_ * DV_ / 4 + 255) / 256, 256>>>();
    gemm_out_mma<<<dim3(16, 8), 256, gemm_smem>>>(out);
}

// round 6
// speedup vs baseline: 1.1422x; 1.1422x over previous
#include <cuda_runtime.h>
#include <cuda_bf16.h>

// ---------------------------------------------------------------------------
// NSA forward. R5: R3's proven register-prefetch MMA GEMM (static smem),
// fused slc+win attention with conflict-free token-major KV tiles,
// fused elementwise/convert launches.
// ---------------------------------------------------------------------------

namespace {
constexpr int S_ = 1024;
constexpr int D_ = 2048;
constexpr int H_ = 32;
constexpr int G_ = 2;
constexpr int HG_ = 16;
constexpr int DQ_ = 128;
constexpr int DV_ = 128;
constexpr int BLK_ = 64;
constexpr int C_ = 16;
constexpr int TOPN_ = 4;
constexpr int WIN_ = 256;
constexpr int NQ_ = H_ * DQ_;   // 4096
constexpr int NKV_ = G_ * DQ_;  // 256
constexpr int NC_ = H_ * 3;     // 96
constexpr float SCALE_ = 0.08838834764831845f;
}

// fp32 scratch
__device__ float g_qraw[S_ * NQ_];
__device__ float g_q[S_ * NQ_];
__device__ float g_kraw[S_ * NKV_];
__device__ float g_k[S_ * NKV_];
__device__ float g_v[S_ * NKV_];
__device__ float g_gates[S_ * NC_];
__device__ float g_kc[C_ * G_ * DQ_];
__device__ float g_vc[C_ * G_ * DV_];
__device__ int   g_idx[S_ * G_ * TOPN_];
__device__ float g_ocomb[S_ * H_ * DV_];

// bf16 split planes
__device__ __align__(16) __nv_bfloat16 g_xh[S_ * D_],  g_xl[S_ * D_];
__device__ __align__(16) __nv_bfloat16 g_Wqh[D_ * NQ_], g_Wql[D_ * NQ_];
__device__ __align__(16) __nv_bfloat16 g_Wkh[D_ * NKV_], g_Wkl[D_ * NKV_];
__device__ __align__(16) __nv_bfloat16 g_Wvh[D_ * NKV_], g_Wvl[D_ * NKV_];
__device__ __align__(16) __nv_bfloat16 g_Wch[D_ * NC_],  g_Wcl[D_ * NC_];
__device__ __align__(16) __nv_bfloat16 g_Woh[H_ * DV_ * D_], g_Wol[H_ * DV_ * D_];
__device__ __align__(16) __nv_bfloat16 g_oh[S_ * H_ * DV_], g_ol[S_ * H_ * DV_];

__device__ __forceinline__ float warp_sum(float v) {
#pragma unroll
    for (int o = 16; o > 0; o >>= 1) v += __shfl_xor_sync(0xffffffffu, v, o);
    return v;
}
__device__ __forceinline__ float warp_max(float v) {
#pragma unroll
    for (int o = 16; o > 0; o >>= 1) v = fmaxf(v, __shfl_xor_sync(0xffffffffu, v, o));
    return v;
}

// ---- tensor-core primitives ------------------------------------------------
__device__ __forceinline__ void ldsm_x4(unsigned (&r)[4], unsigned saddr) {
    asm volatile("ldmatrix.sync.aligned.m8n8.x4.shared.b16 {%0,%1,%2,%3}, [%4];"
                 : "=r"(r[0]), "=r"(r[1]), "=r"(r[2]), "=r"(r[3]) : "r"(saddr));
}
__device__ __forceinline__ void ldsm_x4_t(unsigned (&r)[4], unsigned saddr) {
    asm volatile("ldmatrix.sync.aligned.m8n8.x4.trans.shared.b16 {%0,%1,%2,%3}, [%4];"
                 : "=r"(r[0]), "=r"(r[1]), "=r"(r[2]), "=r"(r[3]) : "r"(saddr));
}
__device__ __forceinline__ void mma_bf16(float (&c)[4], const unsigned (&a)[4],
                                         unsigned b0, unsigned b1) {
    asm volatile(
        "mma.sync.aligned.m16n8k16.row.col.f32.bf16.bf16.f32 "
        "{%0,%1,%2,%3}, {%4,%5,%6,%7}, {%8,%9}, {%0,%1,%2,%3};"
        : "+f"(c[0]), "+f"(c[1]), "+f"(c[2]), "+f"(c[3])
        : "r"(a[0]), "r"(a[1]), "r"(a[2]), "r"(a[3]), "r"(b0), "r"(b1));
}

// ---------------------------------------------------------------------------
// Fused split-convert: one kernel, all 6 fp32 -> (bf16 hi, bf16 lo)
// ---------------------------------------------------------------------------
__global__ __launch_bounds__(256) void cvt_all_kernel(
    const float* __restrict__ x, const float* __restrict__ Wq,
    const float* __restrict__ Wk, const float* __restrict__ Wv,
    const float* __restrict__ Wc, const float* __restrict__ Wo) {
    long long i = (long long)blockIdx.x * 256 + threadIdx.x;
    const float* src;
    __nv_bfloat16 *hi, *lo;
    long long off;
    if (i < 524288)       { src = x;  hi = g_xh;  lo = g_xl;  off = i; }
    else if (i < 2621440) { src = Wq; hi = g_Wqh; lo = g_Wql; off = i - 524288; }
    else if (i < 2752512) { src = Wk; hi = g_Wkh; lo = g_Wkl; off = i - 2621440; }
    else if (i < 2883584) { src = Wv; hi = g_Wvh; lo = g_Wvl; off = i - 2752512; }
    else if (i < 2932736) { src = Wc; hi = g_Wch; lo = g_Wcl; off = i - 2883584; }
    else if (i < 5029888) { src = Wo; hi = g_Woh; lo = g_Wol; off = i - 2932736; }
    else return;
    float4 v = ((const float4*)src)[off];
    __nv_bfloat16 h0 = __float2bfloat16(v.x), h1 = __float2bfloat16(v.y);
    __nv_bfloat16 h2 = __float2bfloat16(v.z), h3 = __float2bfloat16(v.w);
    __nv_bfloat162 a, b;
    a.x = h0; a.y = h1; b.x = h2; b.y = h3;
    ((__nv_bfloat162*)hi)[off * 2] = a;
    ((__nv_bfloat162*)hi)[off * 2 + 1] = b;
    a.x = __float2bfloat16(v.x - __bfloat162float(h0));
    a.y = __float2bfloat16(v.y - __bfloat162float(h1));
    b.x = __float2bfloat16(v.z - __bfloat162float(h2));
    b.y = __float2bfloat16(v.w - __bfloat162float(h3));
    ((__nv_bfloat162*)lo)[off * 2] = a;
    ((__nv_bfloat162*)lo)[off * 2 + 1] = b;
}

__global__ __launch_bounds__(256) void cvt_ocomb_kernel() {
    int i = blockIdx.x * 256 + threadIdx.x;
    if (i >= S_ * H_ * DV_ / 4) return;
    float4 v = ((const float4*)g_ocomb)[i];
    __nv_bfloat16 h0 = __float2bfloat16(v.x), h1 = __float2bfloat16(v.y);
    __nv_bfloat16 h2 = __float2bfloat16(v.z), h3 = __float2bfloat16(v.w);
    __nv_bfloat162 a, b;
    a.x = h0; a.y = h1; b.x = h2; b.y = h3;
    ((__nv_bfloat162*)g_oh)[i * 2] = a;
    ((__nv_bfloat162*)g_oh)[i * 2 + 1] = b;
    a.x = __float2bfloat16(v.x - __bfloat162float(h0));
    a.y = __float2bfloat16(v.y - __bfloat162float(h1));
    b.x = __float2bfloat16(v.z - __bfloat162float(h2));
    b.y = __float2bfloat16(v.w - __bfloat162float(h3));
    ((__nv_bfloat162*)g_ol)[i * 2] = a;
    ((__nv_bfloat162*)g_ol)[i * 2 + 1] = b;
}

// ---------------------------------------------------------------------------
// MMA GEMM tile (R3 proven version): 128x128, K-step 32, 8 warps,
// register-prefetch, static smem.
// ---------------------------------------------------------------------------
struct SmemMMA {
    __nv_bfloat16 Ah[128][40];
    __nv_bfloat16 Al[128][40];
    __nv_bfloat16 Bh[32][136];
    __nv_bfloat16 Bl[32][136];
};

__device__ __forceinline__ void gemm_tile_mma(
    const __nv_bfloat16* __restrict__ Agh, const __nv_bfloat16* __restrict__ Agl,
    int lda,
    const __nv_bfloat16* __restrict__ Bgh, const __nv_bfloat16* __restrict__ Bgl,
    int ldb,
    float* __restrict__ Cp, int ldc,
    int K, int Nloc, int bm, int bn, SmemMMA& sm) {
    const int tid = threadIdx.x;
    const int lane = tid & 31;
    const int w = tid >> 5;
    const int wm = (w >> 1) * 32;
    const int wn = (w & 1) * 64;

    const int ar0 = tid >> 2, ac0 = tid & 3;
    const int ar1 = ar0 + 64;
    const int br0 = tid >> 4, bc0 = tid & 15;
    const int br1 = br0 + 16;
    const bool bok = (bn + bc0 * 8 + 7) < Nloc;

    const unsigned sAh = (unsigned)__cvta_generic_to_shared(&sm.Ah[0][0]);
    const unsigned sAl = (unsigned)__cvta_generic_to_shared(&sm.Al[0][0]);
    const unsigned sBh = (unsigned)__cvta_generic_to_shared(&sm.Bh[0][0]);
    const unsigned sBl = (unsigned)__cvta_generic_to_shared(&sm.Bl[0][0]);

    float c[2][8][4];
#pragma unroll
    for (int i = 0; i < 2; i++)
#pragma unroll
        for (int j = 0; j < 8; j++)
#pragma unroll
            for (int q = 0; q < 4; q++) c[i][j][q] = 0.f;

    uint4 rA0h, rA1h, rA0l, rA1l, rB0h, rB1h, rB0l, rB1l;
    const uint4 uz = make_uint4(0u, 0u, 0u, 0u);

    auto load_tiles = [&](int k0) {
        rA0h = *(const uint4*)(Agh + (size_t)(bm + ar0) * lda + k0 + ac0 * 8);
        rA1h = *(const uint4*)(Agh + (size_t)(bm + ar1) * lda + k0 + ac0 * 8);
        rA0l = *(const uint4*)(Agl + (size_t)(bm + ar0) * lda + k0 + ac0 * 8);
        rA1l = *(const uint4*)(Agl + (size_t)(bm + ar1) * lda + k0 + ac0 * 8);
        if (bok) {
            rB0h = *(const uint4*)(Bgh + (size_t)(k0 + br0) * ldb + bn + bc0 * 8);
            rB1h = *(const uint4*)(Bgh + (size_t)(k0 + br1) * ldb + bn + bc0 * 8);
            rB0l = *(const uint4*)(Bgl + (size_t)(k0 + br0) * ldb + bn + bc0 * 8);
            rB1l = *(const uint4*)(Bgl + (size_t)(k0 + br1) * ldb + bn + bc0 * 8);
        } else {
            rB0h = uz; rB1h = uz; rB0l = uz; rB1l = uz;
        }
    };

    load_tiles(0);
    const int nSteps = K >> 5;
    for (int step = 0; step < nSteps; step++) {
        *(uint4*)&sm.Ah[ar0][ac0 * 8] = rA0h;
        *(uint4*)&sm.Ah[ar1][ac0 * 8] = rA1h;
        *(uint4*)&sm.Al[ar0][ac0 * 8] = rA0l;
        *(uint4*)&sm.Al[ar1][ac0 * 8] = rA1l;
        *(uint4*)&sm.Bh[br0][bc0 * 8] = rB0h;
        *(uint4*)&sm.Bh[br1][bc0 * 8] = rB1h;
        *(uint4*)&sm.Bl[br0][bc0 * 8] = rB0l;
        *(uint4*)&sm.Bl[br1][bc0 * 8] = rB1l;
        __syncthreads();

        if (step + 1 < nSteps) load_tiles((step + 1) * 32);

#pragma unroll
        for (int kk = 0; kk < 2; kk++) {
            unsigned ah[2][4], al[2][4], bh[4][4], bl[4][4];
#pragma unroll
            for (int i = 0; i < 2; i++) {
                unsigned arow = wm + 16 * i + (lane & 15);
                unsigned achunk = kk * 2 + (lane >> 4);
                unsigned off = (arow * 40 + achunk * 8) * 2;
                ldsm_x4(ah[i], sAh + off);
                ldsm_x4(al[i], sAl + off);
            }
#pragma unroll
            for (int j = 0; j < 4; j++) {
                unsigned brow = kk * 16 + (lane & 15);
                unsigned bcol = wn + 16 * j + 8 * (lane >> 4);
                unsigned off = (brow * 136 + bcol) * 2;
                ldsm_x4_t(bh[j], sBh + off);
                ldsm_x4_t(bl[j], sBl + off);
            }
#pragma unroll
            for (int i = 0; i < 2; i++) {
#pragma unroll
                for (int jn = 0; jn < 8; jn++) {
                    const int j = jn >> 1, p = (jn & 1) * 2;
                    mma_bf16(c[i][jn], ah[i], bh[j][p], bh[j][p + 1]);
                    mma_bf16(c[i][jn], ah[i], bl[j][p], bl[j][p + 1]);
                    mma_bf16(c[i][jn], al[i], bh[j][p], bh[j][p + 1]);
                }
            }
        }
        __syncthreads();
    }

    const int qrow = lane >> 2;
    const int qcol = (lane & 3) * 2;
#pragma unroll
    for (int i = 0; i < 2; i++) {
        const int row0 = bm + wm + 16 * i + qrow;
#pragma unroll
        for (int jn = 0; jn < 8; jn++) {
            const int col = bn + wn + jn * 8 + qcol;
            if (col < Nloc) {
                *(float2*)&Cp[(size_t)row0 * ldc + col] =
                    make_float2(c[i][jn][0], c[i][jn][1]);
                *(float2*)&Cp[(size_t)(row0 + 8) * ldc + col] =
                    make_float2(c[i][jn][2], c[i][jn][3]);
            }
        }
    }
}

__global__ __launch_bounds__(256) void fused_proj_mma(
    float* __restrict__ qraw, float* __restrict__ kraw,
    float* __restrict__ v, float* __restrict__ gates) {
    __shared__ SmemMMA sm;
    const int t = blockIdx.x;
    const int bm = blockIdx.y * 128;
    const __nv_bfloat16 *Bh, *Bl;
    float* Cp;
    int Nloc, bn;
    if (t < 32)      { Bh = g_Wqh; Bl = g_Wql; Cp = qraw;  Nloc = NQ_;  bn = t * 128; }
    else if (t < 34) { Bh = g_Wkh; Bl = g_Wkl; Cp = kraw;  Nloc = NKV_; bn = (t - 32) * 128; }
    else if (t < 36) { Bh = g_Wvh; Bl = g_Wvl; Cp = v;     Nloc = NKV_; bn = (t - 34) * 128; }
    else             { Bh = g_Wch; Bl = g_Wcl; Cp = gates; Nloc = NC_;  bn = 0; }
    gemm_tile_mma(g_xh, g_xl, D_, Bh, Bl, Nloc, Cp, Nloc, D_, Nloc, bm, bn, sm);
}

__global__ __launch_bounds__(256) void gemm_out_mma(float* __restrict__ out) {
    __shared__ SmemMMA sm;
    gemm_tile_mma(g_oh, g_ol, H_ * DV_, g_Woh, g_Wol, D_, out, D_,
                  H_ * DV_, D_, blockIdx.y * 128, blockIdx.x * 128, sm);
}

// ---------------------------------------------------------------------------
// Fused elementwise: RoPE(q), RoPE(k), sigmoid(gates).
// ---------------------------------------------------------------------------
__global__ __launch_bounds__(256) void ew_all_kernel(const float* __restrict__ cosp,
                                                     const float* __restrict__ sinp) {
    int i = blockIdx.x * 256 + threadIdx.x;
    if (i < S_ * NQ_) {
        int d = i & 127;
        int s = i >> 12;
        float c = cosp[s * DQ_ + d], sn = sinp[s * DQ_ + d];
        float t = g_qraw[i];
        float rot = (d < 64) ? -g_qraw[i + 64] : g_qraw[i - 64];
        g_q[i] = t * c + rot * sn;
        return;
    }
    i -= S_ * NQ_;
    if (i < S_ * NKV_) {
        int d = i & 127;
        int s = i >> 8;
        float c = cosp[s * DQ_ + d], sn = sinp[s * DQ_ + d];
        float t = g_kraw[i];
        float rot = (d < 64) ? -g_kraw[i + 64] : g_kraw[i - 64];
        g_k[i] = t * c + rot * sn;
        return;
    }
    i -= S_ * NKV_;
    if (i < S_ * NC_) {
        g_gates[i] = 1.f / (1.f + expf(-g_gates[i]));
    }
}

__global__ __launch_bounds__(256) void kcvc_kernel() {
    int i = blockIdx.x * 256 + threadIdx.x;
    if (i >= C_ * G_ * DQ_) return;
    int d = i & 127;
    int g = (i >> 7) & 1;
    int c = i >> 8;
    float sk = 0.f, sv = 0.f;
    for (int j = 0; j < BLK_; j++) {
        int t = c * BLK_ + j;
        sk += g_k[(t * G_ + g) * DQ_ + d];
        sv += g_v[(t * G_ + g) * DV_ + d];
    }
    g_kc[i] = sk * (1.f / 64.f);
    g_vc[i] = sv * (1.f / 64.f);
}

// ---------------------------------------------------------------------------
// Compressed attention + importance + stable top-4 selection (R3 proven).
// ---------------------------------------------------------------------------
__global__ __launch_bounds__(512) void cmp_attn_kernel() {
    const int s = blockIdx.x;
    const int g = blockIdx.y;
    __shared__ float kcs[C_][DQ_];
    __shared__ float vcs[C_][DQ_];
    __shared__ float pw[HG_][C_];
    const int tid = threadIdx.x;

    for (int i = tid; i < C_ * DQ_; i += 512) {
        int c = i >> 7, d = i & 127;
        kcs[c][d] = g_kc[(c * G_ + g) * DQ_ + d];
        vcs[c][d] = g_vc[(c * G_ + g) * DV_ + d];
    }
    __syncthreads();

    const int w = tid >> 5, l = tid & 31;
    const int h = g * HG_ + w;
    const float* qp = &g_q[(s * H_ + h) * DQ_];
    float q0 = qp[l], q1 = qp[l + 32], q2 = qp[l + 64], q3 = qp[l + 96];

    const int ncmp = (s + 1) >> 6;
    float logit[C_];
#pragma unroll
    for (int c = 0; c < C_; c++) {
        if (c < ncmp) {
            float part = q0 * kcs[c][l] + q1 * kcs[c][l + 32] +
                         q2 * kcs[c][l + 64] + q3 * kcs[c][l + 96];
            logit[c] = warp_sum(part) * SCALE_;
        } else {
            logit[c] = -1e30f;
        }
    }
    float m = -1e30f;
#pragma unroll
    for (int c = 0; c < C_; c++) m = fmaxf(m, logit[c]);
    float p[C_];
    float sum = 0.f;
#pragma unroll
    for (int c = 0; c < C_; c++) {
        float e = (logit[c] > -1e29f) ? expf(logit[c] - m) : 0.f;
        p[c] = e;
        sum += e;
    }
    float inv = (sum > 0.f) ? 1.f / sum : 0.f;

    float o0 = 0.f, o1 = 0.f, o2 = 0.f, o3 = 0.f;
#pragma unroll
    for (int c = 0; c < C_; c++) {
        float pc = p[c] * inv;
        o0 += pc * vcs[c][l];
        o1 += pc * vcs[c][l + 32];
        o2 += pc * vcs[c][l + 64];
        o3 += pc * vcs[c][l + 96];
        if (l == 0) pw[w][c] = pc;
    }
    float gate = g_gates[(s * H_ + h) * 3 + 0];
    float* op = &g_ocomb[(s * H_ + h) * DV_];
    op[l]      = gate * o0;
    op[l + 32] = gate * o1;
    op[l + 64] = gate * o2;
    op[l + 96] = gate * o3;
    __syncthreads();

    if (tid == 0) {
        const int cur = s >> 6;
        float imp[C_];
        for (int c = 0; c < C_; c++) {
            float v;
            if (c > cur) v = -1e9f;
            else if (c == 0 || c == cur) v = 1e9f;
            else {
                v = 0.f;
                for (int ww = 0; ww < HG_; ww++) v += pw[ww][c];
            }
            imp[c] = v;
        }
        bool tk[C_];
        for (int c = 0; c < C_; c++) tk[c] = false;
        for (int t = 0; t < TOPN_; t++) {
            float best = -3e38f;
            int bi = 0;
            for (int c = 0; c < C_; c++)
                if (!tk[c] && imp[c] > best) { best = imp[c]; bi = c; }
            tk[bi] = true;
            g_idx[(s * G_ + g) * TOPN_ + t] = bi;
        }
    }
}

// ---------------------------------------------------------------------------
// Fused selected + window attention. Token-major tile kv[64][132] for BOTH
// K (QK: float4 row reads) and V (PV: scalar column reads, (4j+l) mod 32
// distinct per lane). Staging: coalesced float4 LDG + conflict-free STS.128
// (16B-offset j*33+d4, distinct mod 8 within each 8-lane phase).
// ---------------------------------------------------------------------------
struct SlcWinSmem {
    float kv[BLK_][132];
    float qsh[HG_][DQ_];
    int idxs[TOPN_];
};

__device__ __forceinline__ void stage_kv(SlcWinSmem& sm, const float* __restrict__ src,
                                         int t0, int g, int tid) {
    for (int i = tid; i < BLK_ * 32; i += 512) {
        int j = i >> 5, d4 = i & 31;
        float4 v = *(const float4*)&src[((t0 + j) * G_ + g) * DQ_ + d4 * 4];
        *(float4*)&sm.kv[j][d4 * 4] = v;
    }
}

__device__ __forceinline__ void qk_block(const SlcWinSmem& sm, int w, int l,
                                         float& a0, float& a1) {
    a0 = 0.f; a1 = 0.f;
#pragma unroll
    for (int d4 = 0; d4 < 32; d4++) {
        float4 qv = *(const float4*)&sm.qsh[w][d4 * 4];
        float4 k0 = *(const float4*)&sm.kv[l][d4 * 4];
        float4 k1 = *(const float4*)&sm.kv[l + 32][d4 * 4];
        a0 += qv.x * k0.x + qv.y * k0.y + qv.z * k0.z + qv.w * k0.w;
        a1 += qv.x * k1.x + qv.y * k1.y + qv.z * k1.z + qv.w * k1.w;
    }
}

__device__ __forceinline__ void pv_block(const SlcWinSmem& sm, int l,
                                         float p0reg, float p1reg,
                                         float& o0, float& o1, float& o2, float& o3) {
#pragma unroll 8
    for (int j = 0; j < BLK_; j++) {
        float pj = __shfl_sync(0xffffffffu, (j < 32) ? p0reg : p1reg, j & 31);
        o0 += pj * sm.kv[j][l];
        o1 += pj * sm.kv[j][l + 32];
        o2 += pj * sm.kv[j][l + 64];
        o3 += pj * sm.kv[j][l + 96];
    }
}

__global__ __launch_bounds__(512) void slcwin_attn_kernel() {
    const int s = blockIdx.x, g = blockIdx.y;
    __shared__ SlcWinSmem sm;
    const int tid = threadIdx.x;
    const int w = tid >> 5, l = tid & 31;

    for (int i = tid; i < HG_ * 32; i += 512) {
        int hh = i >> 5, d4 = i & 31;
        *(float4*)&sm.qsh[hh][d4 * 4] =
            *(const float4*)&g_q[(s * H_ + g * HG_ + hh) * DQ_ + d4 * 4];
    }
    if (tid < TOPN_) sm.idxs[tid] = g_idx[(s * G_ + g) * TOPN_ + tid];
    __syncthreads();

    int blk[TOPN_];
#pragma unroll
    for (int n = 0; n < TOPN_; n++) blk[n] = sm.idxs[n];

    float ls[8];
    float oS0 = 0.f, oS1 = 0.f, oS2 = 0.f, oS3 = 0.f;

    // ---------------- selected branch ----------------
#pragma unroll
    for (int n = 0; n < TOPN_; n++) {
        const int t0 = blk[n] * BLK_;
        stage_kv(sm, g_k, t0, g, tid);
        __syncthreads();
        float a0, a1;
        qk_block(sm, w, l, a0, a1);
        ls[n * 2 + 0] = (t0 + l <= s) ? a0 * SCALE_ : -1e30f;
        ls[n * 2 + 1] = (t0 + l + 32 <= s) ? a1 * SCALE_ : -1e30f;
        __syncthreads();
    }
    {
        float m = -1e30f;
#pragma unroll
        for (int r = 0; r < 8; r++) m = fmaxf(m, ls[r]);
        m = warp_max(m);
        float sum = 0.f;
#pragma unroll
        for (int r = 0; r < 8; r++) {
            ls[r] = (ls[r] > -1e29f) ? expf(ls[r] - m) : 0.f;
            sum += ls[r];
        }
        sum = warp_sum(sum);
        float inv = 1.f / sum;
#pragma unroll
        for (int r = 0; r < 8; r++) ls[r] *= inv;
    }
#pragma unroll
    for (int n = 0; n < TOPN_; n++) {
        stage_kv(sm, g_v, blk[n] * BLK_, g, tid);
        __syncthreads();
        pv_block(sm, l, ls[n * 2], ls[n * 2 + 1], oS0, oS1, oS2, oS3);
        __syncthreads();
    }

    // ---------------- window branch ----------------
    const int wstart = (s >= WIN_) ? (s - WIN_ + 1) : 0;
    float oW0 = 0.f, oW1 = 0.f, oW2 = 0.f, oW3 = 0.f;
#pragma unroll
    for (int n = 0; n < 4; n++) {
        const int t0 = wstart + n * BLK_;
        stage_kv(sm, g_k, t0, g, tid);
        __syncthreads();
        float a0, a1;
        qk_block(sm, w, l, a0, a1);
        ls[n * 2 + 0] = (t0 + l <= s) ? a0 * SCALE_ : -1e30f;
        ls[n * 2 + 1] = (t0 + l + 32 <= s) ? a1 * SCALE_ : -1e30f;
        __syncthreads();
    }
    {
        float m = -1e30f;
#pragma unroll
        for (int r = 0; r < 8; r++) m = fmaxf(m, ls[r]);
        m = warp_max(m);
        float sum = 0.f;
#pragma unroll
        for (int r = 0; r < 8; r++) {
            ls[r] = (ls[r] > -1e29f) ? expf(ls[r] - m) : 0.f;
            sum += ls[r];
        }
        sum = warp_sum(sum);
        float inv = 1.f / sum;
#pragma unroll
        for (int r = 0; r < 8; r++) ls[r] *= inv;
    }
#pragma unroll
    for (int n = 0; n < 4; n++) {
        stage_kv(sm, g_v, wstart + n * BLK_, g, tid);
        __syncthreads();
        pv_block(sm, l, ls[n * 2], ls[n * 2 + 1], oW0, oW1, oW2, oW3);
        __syncthreads();
    }

    // single RMW combine for both branches
    const int h = g * HG_ + w;
    float g1 = g_gates[(s * H_ + h) * 3 + 1];
    float g2 = g_gates[(s * H_ + h) * 3 + 2];
    float* op = &g_ocomb[(s * H_ + h) * DV_];
    op[l]      += g1 * oS0 + g2 * oW0;
    op[l + 32] += g1 * oS1 + g2 * oW1;
    op[l + 64] += g1 * oS2 + g2 * oW2;
    op[l + 96] += g1 * oS3 + g2 * oW3;
}

// ---------------------------------------------------------------------------
extern "C" void kernel_launch(void* const* d_in, const int* in_sizes, int n_in,
                              void* d_out, int out_size) {
    const float* x    = (const float*)d_in[0];
    const float* cosp = (const float*)d_in[1];
    const float* sinp = (const float*)d_in[2];
    const float* Wq   = (const float*)d_in[3];
    const float* Wk   = (const float*)d_in[4];
    const float* Wv   = (const float*)d_in[5];
    const float* Wc   = (const float*)d_in[6 + 1];  // placeholder; fixed below
    (void)Wc;
    const float* Wo   = (const float*)d_in[6];
    const float* Wc2  = (const float*)d_in[7];
    float* out = (float*)d_out;

    float *p_qraw, *p_kraw, *p_v, *p_gates;
    cudaGetSymbolAddress((void**)&p_qraw, g_qraw);
    cudaGetSymbolAddress((void**)&p_kraw, g_kraw);
    cudaGetSymbolAddress((void**)&p_v, g_v);
    cudaGetSymbolAddress((void**)&p_gates, g_gates);

    // split conversions (one launch)
    cvt_all_kernel<<<(5029888 + 255) / 256, 256>>>(x, Wq, Wk, Wv, Wc2, Wo);

    // fused projections: 37 n-tiles x 8 m-tiles
    fused_proj_mma<<<dim3(37, 8), 256>>>(p_qraw, p_kraw, p_v, p_gates);

    // fused elementwise (rope q, rope k, sigmoid) + block means
    ew_all_kernel<<<(S_ * NQ_ + S_ * NKV_ + S_ * NC_ + 255) / 256, 256>>>(cosp, sinp);
    kcvc_kernel<<<(C_ * G_ * DQ_ + 255) / 256, 256>>>();

    // attention
    cmp_attn_kernel<<<dim3(S_, G_), 512>>>();
    slcwin_attn_kernel<<<dim3(S_, G_), 512>>>();

    // split ocomb, output projection
    cvt_ocomb_kernel<<<(S_ * H_ * DV_ / 4 + 255) / 256, 256>>>();
    gemm_out_mma<<<dim3(16, 8), 256>>>(out);
}

// round 11
// speedup vs baseline: 1.1508x; 1.0075x over previous
#include <cuda_runtime.h>
#include <cuda_bf16.h>

// ---------------------------------------------------------------------------
// NSA forward. R7: R5 baseline (proven 1081us) with the GEMM staging moved to
// cp.async 2-stage double buffering + __launch_bounds__(256,2) for 2 CTA/SM.
// tcgen05 is NOT available (harness PTX target lacks the 'a' feature suffix).
// ---------------------------------------------------------------------------

namespace {
constexpr int S_ = 1024;
constexpr int D_ = 2048;
constexpr int H_ = 32;
constexpr int G_ = 2;
constexpr int HG_ = 16;
constexpr int DQ_ = 128;
constexpr int DV_ = 128;
constexpr int BLK_ = 64;
constexpr int C_ = 16;
constexpr int TOPN_ = 4;
constexpr int WIN_ = 256;
constexpr int NQ_ = H_ * DQ_;   // 4096
constexpr int NKV_ = G_ * DQ_;  // 256
constexpr int NC_ = H_ * 3;     // 96
constexpr float SCALE_ = 0.08838834764831845f;

// GEMM smem: per stage Ah(8K sw64) Al(8K) Bh(8.5K) Bl(8.5K) = 33792 B
constexpr unsigned OFF_AL = 8192;
constexpr unsigned OFF_BH = 16384;
constexpr unsigned OFF_BL = 25088;
constexpr unsigned STAGE_BYTES = 33792;
constexpr unsigned GEMM_SMEM = 2 * STAGE_BYTES;  // 67584
}

// fp32 scratch
__device__ float g_qraw[S_ * NQ_];
__device__ float g_q[S_ * NQ_];
__device__ float g_kraw[S_ * NKV_];
__device__ float g_k[S_ * NKV_];
__device__ float g_v[S_ * NKV_];
__device__ float g_gates[S_ * NC_];
__device__ float g_kc[C_ * G_ * DQ_];
__device__ float g_vc[C_ * G_ * DV_];
__device__ int   g_idx[S_ * G_ * TOPN_];
__device__ float g_ocomb[S_ * H_ * DV_];

// bf16 split planes
__device__ __align__(16) __nv_bfloat16 g_xh[S_ * D_],  g_xl[S_ * D_];
__device__ __align__(16) __nv_bfloat16 g_Wqh[D_ * NQ_], g_Wql[D_ * NQ_];
__device__ __align__(16) __nv_bfloat16 g_Wkh[D_ * NKV_], g_Wkl[D_ * NKV_];
__device__ __align__(16) __nv_bfloat16 g_Wvh[D_ * NKV_], g_Wvl[D_ * NKV_];
__device__ __align__(16) __nv_bfloat16 g_Wch[D_ * NC_],  g_Wcl[D_ * NC_];
__device__ __align__(16) __nv_bfloat16 g_Woh[H_ * DV_ * D_], g_Wol[H_ * DV_ * D_];
__device__ __align__(16) __nv_bfloat16 g_oh[S_ * H_ * DV_], g_ol[S_ * H_ * DV_];

__device__ __forceinline__ float warp_sum(float v) {
#pragma unroll
    for (int o = 16; o > 0; o >>= 1) v += __shfl_xor_sync(0xffffffffu, v, o);
    return v;
}
__device__ __forceinline__ float warp_max(float v) {
#pragma unroll
    for (int o = 16; o > 0; o >>= 1) v = fmaxf(v, __shfl_xor_sync(0xffffffffu, v, o));
    return v;
}

// ---- tensor-core / async primitives ---------------------------------------
__device__ __forceinline__ void ldsm_x4(unsigned (&r)[4], unsigned saddr) {
    asm volatile("ldmatrix.sync.aligned.m8n8.x4.shared.b16 {%0,%1,%2,%3}, [%4];"
                 : "=r"(r[0]), "=r"(r[1]), "=r"(r[2]), "=r"(r[3]) : "r"(saddr));
}
__device__ __forceinline__ void ldsm_x4_t(unsigned (&r)[4], unsigned saddr) {
    asm volatile("ldmatrix.sync.aligned.m8n8.x4.trans.shared.b16 {%0,%1,%2,%3}, [%4];"
                 : "=r"(r[0]), "=r"(r[1]), "=r"(r[2]), "=r"(r[3]) : "r"(saddr));
}
__device__ __forceinline__ void mma_bf16(float (&c)[4], const unsigned (&a)[4],
                                         unsigned b0, unsigned b1) {
    asm volatile(
        "mma.sync.aligned.m16n8k16.row.col.f32.bf16.bf16.f32 "
        "{%0,%1,%2,%3}, {%4,%5,%6,%7}, {%8,%9}, {%0,%1,%2,%3};"
        : "+f"(c[0]), "+f"(c[1]), "+f"(c[2]), "+f"(c[3])
        : "r"(a[0]), "r"(a[1]), "r"(a[2]), "r"(a[3]), "r"(b0), "r"(b1));
}
__device__ __forceinline__ void cp16(unsigned dst, const void* src, bool valid) {
    int sz = valid ? 16 : 0;
    asm volatile("cp.async.cg.shared.global [%0], [%1], 16, %2;"
                 :: "r"(dst), "l"(src), "r"(sz));
}
#define CP_COMMIT() asm volatile("cp.async.commit_group;")
#define CP_WAIT(n) asm volatile("cp.async.wait_group %0;" :: "n"(n))

// A-tile swizzle: row stride 64B, 16B chunk xor'd by row pair -> ldsm-clean
__device__ __forceinline__ unsigned swA(int r, int c) {
    return (unsigned)(r * 64) + ((unsigned)(c ^ ((r >> 1) & 3)) << 4);
}

// ---------------------------------------------------------------------------
// Fused split-convert: one kernel, all 6 fp32 -> (bf16 hi, bf16 lo)
// ---------------------------------------------------------------------------
__global__ __launch_bounds__(256) void cvt_all_kernel(
    const float* __restrict__ x, const float* __restrict__ Wq,
    const float* __restrict__ Wk, const float* __restrict__ Wv,
    const float* __restrict__ Wc, const float* __restrict__ Wo) {
    long long i = (long long)blockIdx.x * 256 + threadIdx.x;
    const float* src;
    __nv_bfloat16 *hi, *lo;
    long long off;
    if (i < 524288)       { src = x;  hi = g_xh;  lo = g_xl;  off = i; }
    else if (i < 2621440) { src = Wq; hi = g_Wqh; lo = g_Wql; off = i - 524288; }
    else if (i < 2752512) { src = Wk; hi = g_Wkh; lo = g_Wkl; off = i - 2621440; }
    else if (i < 2883584) { src = Wv; hi = g_Wvh; lo = g_Wvl; off = i - 2752512; }
    else if (i < 2932736) { src = Wc; hi = g_Wch; lo = g_Wcl; off = i - 2883584; }
    else if (i < 5029888) { src = Wo; hi = g_Woh; lo = g_Wol; off = i - 2932736; }
    else return;
    float4 v = ((const float4*)src)[off];
    __nv_bfloat16 h0 = __float2bfloat16(v.x), h1 = __float2bfloat16(v.y);
    __nv_bfloat16 h2 = __float2bfloat16(v.z), h3 = __float2bfloat16(v.w);
    __nv_bfloat162 a, b;
    a.x = h0; a.y = h1; b.x = h2; b.y = h3;
    ((__nv_bfloat162*)hi)[off * 2] = a;
    ((__nv_bfloat162*)hi)[off * 2 + 1] = b;
    a.x = __float2bfloat16(v.x - __bfloat162float(h0));
    a.y = __float2bfloat16(v.y - __bfloat162float(h1));
    b.x = __float2bfloat16(v.z - __bfloat162float(h2));
    b.y = __float2bfloat16(v.w - __bfloat162float(h3));
    ((__nv_bfloat162*)lo)[off * 2] = a;
    ((__nv_bfloat162*)lo)[off * 2 + 1] = b;
}

__global__ __launch_bounds__(256) void cvt_ocomb_kernel() {
    int i = blockIdx.x * 256 + threadIdx.x;
    if (i >= S_ * H_ * DV_ / 4) return;
    float4 v = ((const float4*)g_ocomb)[i];
    __nv_bfloat16 h0 = __float2bfloat16(v.x), h1 = __float2bfloat16(v.y);
    __nv_bfloat16 h2 = __float2bfloat16(v.z), h3 = __float2bfloat16(v.w);
    __nv_bfloat162 a, b;
    a.x = h0; a.y = h1; b.x = h2; b.y = h3;
    ((__nv_bfloat162*)g_oh)[i * 2] = a;
    ((__nv_bfloat162*)g_oh)[i * 2 + 1] = b;
    a.x = __float2bfloat16(v.x - __bfloat162float(h0));
    a.y = __float2bfloat16(v.y - __bfloat162float(h1));
    b.x = __float2bfloat16(v.z - __bfloat162float(h2));
    b.y = __float2bfloat16(v.w - __bfloat162float(h3));
    ((__nv_bfloat162*)g_ol)[i * 2] = a;
    ((__nv_bfloat162*)g_ol)[i * 2 + 1] = b;
}

// ---------------------------------------------------------------------------
// cp.async double-buffered MMA GEMM. 128x128 tile, K-step 32, 8 warps,
// 3-term split-bf16. 2 CTAs/SM via launch bounds.
// ---------------------------------------------------------------------------
__device__ __forceinline__ void gemm_tile_async(
    const __nv_bfloat16* __restrict__ Agh, const __nv_bfloat16* __restrict__ Agl,
    int lda,
    const __nv_bfloat16* __restrict__ Bgh, const __nv_bfloat16* __restrict__ Bgl,
    int ldb,
    float* __restrict__ Cp, int ldc,
    int K, int Nloc, int bm, int bn, char* dynsm) {
    const int tid = threadIdx.x;
    const int lane = tid & 31;
    const int w = tid >> 5;
    const int wm = (w >> 1) * 32;
    const int wn = (w & 1) * 64;

    const int ar0 = tid >> 2, ac0 = tid & 3;   // A rows 0..63, 16B chunk 0..3
    const int ar1 = ar0 + 64;
    const int br0 = tid >> 4, bc0 = tid & 15;  // B rows 0..15, 16B chunk 0..15
    const int br1 = br0 + 16;
    const bool bok = (bn + bc0 * 8 + 7) < Nloc;

    const unsigned sbase = (unsigned)__cvta_generic_to_shared(dynsm);

    float c[2][8][4];
#pragma unroll
    for (int i = 0; i < 2; i++)
#pragma unroll
        for (int j = 0; j < 8; j++)
#pragma unroll
            for (int q = 0; q < 4; q++) c[i][j][q] = 0.f;

    auto issue = [&](int step, int stage) {
        const unsigned base = sbase + stage * STAGE_BYTES;
        const int k0 = step * 32;
        cp16(base + swA(ar0, ac0), Agh + (size_t)(bm + ar0) * lda + k0 + ac0 * 8, true);
        cp16(base + swA(ar1, ac0), Agh + (size_t)(bm + ar1) * lda + k0 + ac0 * 8, true);
        cp16(base + OFF_AL + swA(ar0, ac0), Agl + (size_t)(bm + ar0) * lda + k0 + ac0 * 8, true);
        cp16(base + OFF_AL + swA(ar1, ac0), Agl + (size_t)(bm + ar1) * lda + k0 + ac0 * 8, true);
        const __nv_bfloat16* b0 = bok ? Bgh + (size_t)(k0 + br0) * ldb + bn + bc0 * 8 : Bgh;
        const __nv_bfloat16* b1 = bok ? Bgh + (size_t)(k0 + br1) * ldb + bn + bc0 * 8 : Bgh;
        const __nv_bfloat16* b2 = bok ? Bgl + (size_t)(k0 + br0) * ldb + bn + bc0 * 8 : Bgl;
        const __nv_bfloat16* b3 = bok ? Bgl + (size_t)(k0 + br1) * ldb + bn + bc0 * 8 : Bgl;
        cp16(base + OFF_BH + br0 * 272 + bc0 * 16, b0, bok);
        cp16(base + OFF_BH + br1 * 272 + bc0 * 16, b1, bok);
        cp16(base + OFF_BL + br0 * 272 + bc0 * 16, b2, bok);
        cp16(base + OFF_BL + br1 * 272 + bc0 * 16, b3, bok);
    };

    const int nSteps = K >> 5;
    issue(0, 0);
    CP_COMMIT();

    for (int step = 0; step < nSteps; step++) {
        const int cur = step & 1;
        if (step + 1 < nSteps) {
            issue(step + 1, cur ^ 1);
            CP_COMMIT();
            CP_WAIT(1);
        } else {
            CP_WAIT(0);
        }
        __syncthreads();

        const unsigned base = sbase + cur * STAGE_BYTES;
#pragma unroll
        for (int kk = 0; kk < 2; kk++) {
            unsigned ah[2][4], al[2][4], bh[4][4], bl[4][4];
#pragma unroll
            for (int i = 0; i < 2; i++) {
                int arow = wm + 16 * i + (lane & 15);
                int achunk = kk * 2 + (lane >> 4);
                unsigned off = swA(arow, achunk);
                ldsm_x4(ah[i], base + off);
                ldsm_x4(al[i], base + OFF_AL + off);
            }
#pragma unroll
            for (int j = 0; j < 4; j++) {
                unsigned brow = kk * 16 + (lane & 15);
                unsigned bcol = wn + 16 * j + 8 * (lane >> 4);
                unsigned off = brow * 272 + bcol * 2;
                ldsm_x4_t(bh[j], base + OFF_BH + off);
                ldsm_x4_t(bl[j], base + OFF_BL + off);
            }
#pragma unroll
            for (int i = 0; i < 2; i++) {
#pragma unroll
                for (int jn = 0; jn < 8; jn++) {
                    const int j = jn >> 1, p = (jn & 1) * 2;
                    mma_bf16(c[i][jn], ah[i], bh[j][p], bh[j][p + 1]);
                    mma_bf16(c[i][jn], ah[i], bl[j][p], bl[j][p + 1]);
                    mma_bf16(c[i][jn], al[i], bh[j][p], bh[j][p + 1]);
                }
            }
        }
        __syncthreads();
    }

    const int qrow = lane >> 2;
    const int qcol = (lane & 3) * 2;
#pragma unroll
    for (int i = 0; i < 2; i++) {
        const int row0 = bm + wm + 16 * i + qrow;
#pragma unroll
        for (int jn = 0; jn < 8; jn++) {
            const int col = bn + wn + jn * 8 + qcol;
            if (col < Nloc) {
                *(float2*)&Cp[(size_t)row0 * ldc + col] =
                    make_float2(c[i][jn][0], c[i][jn][1]);
                *(float2*)&Cp[(size_t)(row0 + 8) * ldc + col] =
                    make_float2(c[i][jn][2], c[i][jn][3]);
            }
        }
    }
}

__global__ __launch_bounds__(256, 2) void fused_proj_mma(
    float* __restrict__ qraw, float* __restrict__ kraw,
    float* __restrict__ v, float* __restrict__ gates) {
    extern __shared__ char dynsm[];
    const int t = blockIdx.x;
    const int bm = blockIdx.y * 128;
    const __nv_bfloat16 *Bh, *Bl;
    float* Cp;
    int Nloc, bn;
    if (t < 32)      { Bh = g_Wqh; Bl = g_Wql; Cp = qraw;  Nloc = NQ_;  bn = t * 128; }
    else if (t < 34) { Bh = g_Wkh; Bl = g_Wkl; Cp = kraw;  Nloc = NKV_; bn = (t - 32) * 128; }
    else if (t < 36) { Bh = g_Wvh; Bl = g_Wvl; Cp = v;     Nloc = NKV_; bn = (t - 34) * 128; }
    else             { Bh = g_Wch; Bl = g_Wcl; Cp = gates; Nloc = NC_;  bn = 0; }
    gemm_tile_async(g_xh, g_xl, D_, Bh, Bl, Nloc, Cp, Nloc, D_, Nloc, bm, bn, dynsm);
}

__global__ __launch_bounds__(256, 2) void gemm_out_mma(float* __restrict__ out) {
    extern __shared__ char dynsm[];
    gemm_tile_async(g_oh, g_ol, H_ * DV_, g_Woh, g_Wol, D_, out, D_,
                    H_ * DV_, D_, blockIdx.y * 128, blockIdx.x * 128, dynsm);
}

// ---------------------------------------------------------------------------
// Fused elementwise: RoPE(q), RoPE(k), sigmoid(gates).
// ---------------------------------------------------------------------------
__global__ __launch_bounds__(256) void ew_all_kernel(const float* __restrict__ cosp,
                                                     const float* __restrict__ sinp) {
    int i = blockIdx.x * 256 + threadIdx.x;
    if (i < S_ * NQ_) {
        int d = i & 127;
        int s = i >> 12;
        float c = cosp[s * DQ_ + d], sn = sinp[s * DQ_ + d];
        float t = g_qraw[i];
        float rot = (d < 64) ? -g_qraw[i + 64] : g_qraw[i - 64];
        g_q[i] = t * c + rot * sn;
        return;
    }
    i -= S_ * NQ_;
    if (i < S_ * NKV_) {
        int d = i & 127;
        int s = i >> 8;
        float c = cosp[s * DQ_ + d], sn = sinp[s * DQ_ + d];
        float t = g_kraw[i];
        float rot = (d < 64) ? -g_kraw[i + 64] : g_kraw[i - 64];
        g_k[i] = t * c + rot * sn;
        return;
    }
    i -= S_ * NKV_;
    if (i < S_ * NC_) {
        g_gates[i] = 1.f / (1.f + expf(-g_gates[i]));
    }
}

__global__ __launch_bounds__(256) void kcvc_kernel() {
    int i = blockIdx.x * 256 + threadIdx.x;
    if (i >= C_ * G_ * DQ_) return;
    int d = i & 127;
    int g = (i >> 7) & 1;
    int c = i >> 8;
    float sk = 0.f, sv = 0.f;
    for (int j = 0; j < BLK_; j++) {
        int t = c * BLK_ + j;
        sk += g_k[(t * G_ + g) * DQ_ + d];
        sv += g_v[(t * G_ + g) * DV_ + d];
    }
    g_kc[i] = sk * (1.f / 64.f);
    g_vc[i] = sv * (1.f / 64.f);
}

// ---------------------------------------------------------------------------
// Compressed attention + importance + stable top-4 selection (proven).
// ---------------------------------------------------------------------------
__global__ __launch_bounds__(512) void cmp_attn_kernel() {
    const int s = blockIdx.x;
    const int g = blockIdx.y;
    __shared__ float kcs[C_][DQ_];
    __shared__ float vcs[C_][DQ_];
    __shared__ float pw[HG_][C_];
    const int tid = threadIdx.x;

    for (int i = tid; i < C_ * DQ_; i += 512) {
        int c = i >> 7, d = i & 127;
        kcs[c][d] = g_kc[(c * G_ + g) * DQ_ + d];
        vcs[c][d] = g_vc[(c * G_ + g) * DV_ + d];
    }
    __syncthreads();

    const int w = tid >> 5, l = tid & 31;
    const int h = g * HG_ + w;
    const float* qp = &g_q[(s * H_ + h) * DQ_];
    float q0 = qp[l], q1 = qp[l + 32], q2 = qp[l + 64], q3 = qp[l + 96];

    const int ncmp = (s + 1) >> 6;
    float logit[C_];
#pragma unroll
    for (int c = 0; c < C_; c++) {
        if (c < ncmp) {
            float part = q0 * kcs[c][l] + q1 * kcs[c][l + 32] +
                         q2 * kcs[c][l + 64] + q3 * kcs[c][l + 96];
            logit[c] = warp_sum(part) * SCALE_;
        } else {
            logit[c] = -1e30f;
        }
    }
    float m = -1e30f;
#pragma unroll
    for (int c = 0; c < C_; c++) m = fmaxf(m, logit[c]);
    float p[C_];
    float sum = 0.f;
#pragma unroll
    for (int c = 0; c < C_; c++) {
        float e = (logit[c] > -1e29f) ? expf(logit[c] - m) : 0.f;
        p[c] = e;
        sum += e;
    }
    float inv = (sum > 0.f) ? 1.f / sum : 0.f;

    float o0 = 0.f, o1 = 0.f, o2 = 0.f, o3 = 0.f;
#pragma unroll
    for (int c = 0; c < C_; c++) {
        float pc = p[c] * inv;
        o0 += pc * vcs[c][l];
        o1 += pc * vcs[c][l + 32];
        o2 += pc * vcs[c][l + 64];
        o3 += pc * vcs[c][l + 96];
        if (l == 0) pw[w][c] = pc;
    }
    float gate = g_gates[(s * H_ + h) * 3 + 0];
    float* op = &g_ocomb[(s * H_ + h) * DV_];
    op[l]      = gate * o0;
    op[l + 32] = gate * o1;
    op[l + 64] = gate * o2;
    op[l + 96] = gate * o3;
    __syncthreads();

    if (tid == 0) {
        const int cur = s >> 6;
        float imp[C_];
        for (int c = 0; c < C_; c++) {
            float v;
            if (c > cur) v = -1e9f;
            else if (c == 0 || c == cur) v = 1e9f;
            else {
                v = 0.f;
                for (int ww = 0; ww < HG_; ww++) v += pw[ww][c];
            }
            imp[c] = v;
        }
        bool tk[C_];
        for (int c = 0; c < C_; c++) tk[c] = false;
        for (int t = 0; t < TOPN_; t++) {
            float best = -3e38f;
            int bi = 0;
            for (int c = 0; c < C_; c++)
                if (!tk[c] && imp[c] > best) { best = imp[c]; bi = c; }
            tk[bi] = true;
            g_idx[(s * G_ + g) * TOPN_ + t] = bi;
        }
    }
}

// ---------------------------------------------------------------------------
// Fused selected + window attention (proven R5 layout).
// ---------------------------------------------------------------------------
struct SlcWinSmem {
    float kv[BLK_][132];
    float qsh[HG_][DQ_];
    int idxs[TOPN_];
};

__device__ __forceinline__ void stage_kv(SlcWinSmem& sm, const float* __restrict__ src,
                                         int t0, int g, int tid) {
    for (int i = tid; i < BLK_ * 32; i += 512) {
        int j = i >> 5, d4 = i & 31;
        float4 v = *(const float4*)&src[((t0 + j) * G_ + g) * DQ_ + d4 * 4];
        *(float4*)&sm.kv[j][d4 * 4] = v;
    }
}

__device__ __forceinline__ void qk_block(const SlcWinSmem& sm, int w, int l,
                                         float& a0, float& a1) {
    a0 = 0.f; a1 = 0.f;
#pragma unroll
    for (int d4 = 0; d4 < 32; d4++) {
        float4 qv = *(const float4*)&sm.qsh[w][d4 * 4];
        float4 k0 = *(const float4*)&sm.kv[l][d4 * 4];
        float4 k1 = *(const float4*)&sm.kv[l + 32][d4 * 4];
        a0 += qv.x * k0.x + qv.y * k0.y + qv.z * k0.z + qv.w * k0.w;
        a1 += qv.x * k1.x + qv.y * k1.y + qv.z * k1.z + qv.w * k1.w;
    }
}

__device__ __forceinline__ void pv_block(const SlcWinSmem& sm, int l,
                                         float p0reg, float p1reg,
                                         float& o0, float& o1, float& o2, float& o3) {
#pragma unroll 8
    for (int j = 0; j < BLK_; j++) {
        float pj = __shfl_sync(0xffffffffu, (j < 32) ? p0reg : p1reg, j & 31);
        o0 += pj * sm.kv[j][l];
        o1 += pj * sm.kv[j][l + 32];
        o2 += pj * sm.kv[j][l + 64];
        o3 += pj * sm.kv[j][l + 96];
    }
}

__global__ __launch_bounds__(512) void slcwin_attn_kernel() {
    const int s = blockIdx.x, g = blockIdx.y;
    __shared__ SlcWinSmem sm;
    const int tid = threadIdx.x;
    const int w = tid >> 5, l = tid & 31;

    for (int i = tid; i < HG_ * 32; i += 512) {
        int hh = i >> 5, d4 = i & 31;
        *(float4*)&sm.qsh[hh][d4 * 4] =
            *(const float4*)&g_q[(s * H_ + g * HG_ + hh) * DQ_ + d4 * 4];
    }
    if (tid < TOPN_) sm.idxs[tid] = g_idx[(s * G_ + g) * TOPN_ + tid];
    __syncthreads();

    int blk[TOPN_];
#pragma unroll
    for (int n = 0; n < TOPN_; n++) blk[n] = sm.idxs[n];

    float ls[8];
    float oS0 = 0.f, oS1 = 0.f, oS2 = 0.f, oS3 = 0.f;

    // selected branch
#pragma unroll
    for (int n = 0; n < TOPN_; n++) {
        const int t0 = blk[n] * BLK_;
        stage_kv(sm, g_k, t0, g, tid);
        __syncthreads();
        float a0, a1;
        qk_block(sm, w, l, a0, a1);
        ls[n * 2 + 0] = (t0 + l <= s) ? a0 * SCALE_ : -1e30f;
        ls[n * 2 + 1] = (t0 + l + 32 <= s) ? a1 * SCALE_ : -1e30f;
        __syncthreads();
    }
    {
        float m = -1e30f;
#pragma unroll
        for (int r = 0; r < 8; r++) m = fmaxf(m, ls[r]);
        m = warp_max(m);
        float sum = 0.f;
#pragma unroll
        for (int r = 0; r < 8; r++) {
            ls[r] = (ls[r] > -1e29f) ? expf(ls[r] - m) : 0.f;
            sum += ls[r];
        }
        sum = warp_sum(sum);
        float inv = 1.f / sum;
#pragma unroll
        for (int r = 0; r < 8; r++) ls[r] *= inv;
    }
#pragma unroll
    for (int n = 0; n < TOPN_; n++) {
        stage_kv(sm, g_v, blk[n] * BLK_, g, tid);
        __syncthreads();
        pv_block(sm, l, ls[n * 2], ls[n * 2 + 1], oS0, oS1, oS2, oS3);
        __syncthreads();
    }

    // window branch
    const int wstart = (s >= WIN_) ? (s - WIN_ + 1) : 0;
    float oW0 = 0.f, oW1 = 0.f, oW2 = 0.f, oW3 = 0.f;
#pragma unroll
    for (int n = 0; n < 4; n++) {
        const int t0 = wstart + n * BLK_;
        stage_kv(sm, g_k, t0, g, tid);
        __syncthreads();
        float a0, a1;
        qk_block(sm, w, l, a0, a1);
        ls[n * 2 + 0] = (t0 + l <= s) ? a0 * SCALE_ : -1e30f;
        ls[n * 2 + 1] = (t0 + l + 32 <= s) ? a1 * SCALE_ : -1e30f;
        __syncthreads();
    }
    {
        float m = -1e30f;
#pragma unroll
        for (int r = 0; r < 8; r++) m = fmaxf(m, ls[r]);
        m = warp_max(m);
        float sum = 0.f;
#pragma unroll
        for (int r = 0; r < 8; r++) {
            ls[r] = (ls[r] > -1e29f) ? expf(ls[r] - m) : 0.f;
            sum += ls[r];
        }
        sum = warp_sum(sum);
        float inv = 1.f / sum;
#pragma unroll
        for (int r = 0; r < 8; r++) ls[r] *= inv;
    }
#pragma unroll
    for (int n = 0; n < 4; n++) {
        stage_kv(sm, g_v, wstart + n * BLK_, g, tid);
        __syncthreads();
        pv_block(sm, l, ls[n * 2], ls[n * 2 + 1], oW0, oW1, oW2, oW3);
        __syncthreads();
    }

    const int h = g * HG_ + w;
    float g1 = g_gates[(s * H_ + h) * 3 + 1];
    float g2 = g_gates[(s * H_ + h) * 3 + 2];
    float* op = &g_ocomb[(s * H_ + h) * DV_];
    op[l]      += g1 * oS0 + g2 * oW0;
    op[l + 32] += g1 * oS1 + g2 * oW1;
    op[l + 64] += g1 * oS2 + g2 * oW2;
    op[l + 96] += g1 * oS3 + g2 * oW3;
}

// ---------------------------------------------------------------------------
extern "C" void kernel_launch(void* const* d_in, const int* in_sizes, int n_in,
                              void* d_out, int out_size) {
    const float* x    = (const float*)d_in[0];
    const float* cosp = (const float*)d_in[1];
    const float* sinp = (const float*)d_in[2];
    const float* Wq   = (const float*)d_in[3];
    const float* Wk   = (const float*)d_in[4];
    const float* Wv   = (const float*)d_in[5];
    const float* Wo   = (const float*)d_in[6];
    const float* Wc   = (const float*)d_in[7];
    float* out = (float*)d_out;

    float *p_qraw, *p_kraw, *p_v, *p_gates;
    cudaGetSymbolAddress((void**)&p_qraw, g_qraw);
    cudaGetSymbolAddress((void**)&p_kraw, g_kraw);
    cudaGetSymbolAddress((void**)&p_v, g_v);
    cudaGetSymbolAddress((void**)&p_gates, g_gates);

    cudaFuncSetAttribute(fused_proj_mma,
                         cudaFuncAttributeMaxDynamicSharedMemorySize, GEMM_SMEM);
    cudaFuncSetAttribute(gemm_out_mma,
                         cudaFuncAttributeMaxDynamicSharedMemorySize, GEMM_SMEM);

    // split conversions (one launch)
    cvt_all_kernel<<<(5029888 + 255) / 256, 256>>>(x, Wq, Wk, Wv, Wc, Wo);

    // fused projections: 37 n-tiles x 8 m-tiles
    fused_proj_mma<<<dim3(37, 8), 256, GEMM_SMEM>>>(p_qraw, p_kraw, p_v, p_gates);

    // fused elementwise (rope q, rope k, sigmoid) + block means
    ew_all_kernel<<<(S_ * NQ_ + S_ * NKV_ + S_ * NC_ + 255) / 256, 256>>>(cosp, sinp);
    kcvc_kernel<<<(C_ * G_ * DQ_ + 255) / 256, 256>>>();

    // attention
    cmp_attn_kernel<<<dim3(S_, G_), 512>>>();
    slcwin_attn_kernel<<<dim3(S_, G_), 512>>>();

    // split ocomb, output projection
    cvt_ocomb_kernel<<<(S_ * H_ * DV_ / 4 + 255) / 256, 256>>>();
    gemm_out_mma<<<dim3(16, 8), 256, GEMM_SMEM>>>(out);
}

// round 12
// speedup vs baseline: 1.1865x; 1.0310x over previous
#include <cuda_runtime.h>
#include <cuda_bf16.h>

// ---------------------------------------------------------------------------
// NSA forward. R8: GEMM inner loop reordered term-major + non-volatile mma
// (breaks accumulator RAW serialization); cvt split into 3 launches so the
// profiler slot (4th launch) lands on fused_proj_mma.
// ---------------------------------------------------------------------------

namespace {
constexpr int S_ = 1024;
constexpr int D_ = 2048;
constexpr int H_ = 32;
constexpr int G_ = 2;
constexpr int HG_ = 16;
constexpr int DQ_ = 128;
constexpr int DV_ = 128;
constexpr int BLK_ = 64;
constexpr int C_ = 16;
constexpr int TOPN_ = 4;
constexpr int WIN_ = 256;
constexpr int NQ_ = H_ * DQ_;   // 4096
constexpr int NKV_ = G_ * DQ_;  // 256
constexpr int NC_ = H_ * 3;     // 96
constexpr float SCALE_ = 0.08838834764831845f;

constexpr unsigned OFF_AL = 8192;
constexpr unsigned OFF_BH = 16384;
constexpr unsigned OFF_BL = 25088;
constexpr unsigned STAGE_BYTES = 33792;
constexpr unsigned GEMM_SMEM = 2 * STAGE_BYTES;  // 67584
}

// fp32 scratch
__device__ float g_qraw[S_ * NQ_];
__device__ float g_q[S_ * NQ_];
__device__ float g_kraw[S_ * NKV_];
__device__ float g_k[S_ * NKV_];
__device__ float g_v[S_ * NKV_];
__device__ float g_gates[S_ * NC_];
__device__ float g_kc[C_ * G_ * DQ_];
__device__ float g_vc[C_ * G_ * DV_];
__device__ int   g_idx[S_ * G_ * TOPN_];
__device__ float g_ocomb[S_ * H_ * DV_];

// bf16 split planes
__device__ __align__(16) __nv_bfloat16 g_xh[S_ * D_],  g_xl[S_ * D_];
__device__ __align__(16) __nv_bfloat16 g_Wqh[D_ * NQ_], g_Wql[D_ * NQ_];
__device__ __align__(16) __nv_bfloat16 g_Wkh[D_ * NKV_], g_Wkl[D_ * NKV_];
__device__ __align__(16) __nv_bfloat16 g_Wvh[D_ * NKV_], g_Wvl[D_ * NKV_];
__device__ __align__(16) __nv_bfloat16 g_Wch[D_ * NC_],  g_Wcl[D_ * NC_];
__device__ __align__(16) __nv_bfloat16 g_Woh[H_ * DV_ * D_], g_Wol[H_ * DV_ * D_];
__device__ __align__(16) __nv_bfloat16 g_oh[S_ * H_ * DV_], g_ol[S_ * H_ * DV_];

__device__ __forceinline__ float warp_sum(float v) {
#pragma unroll
    for (int o = 16; o > 0; o >>= 1) v += __shfl_xor_sync(0xffffffffu, v, o);
    return v;
}
__device__ __forceinline__ float warp_max(float v) {
#pragma unroll
    for (int o = 16; o > 0; o >>= 1) v = fmaxf(v, __shfl_xor_sync(0xffffffffu, v, o));
    return v;
}

// ---- tensor-core / async primitives ---------------------------------------
__device__ __forceinline__ void ldsm_x4(unsigned (&r)[4], unsigned saddr) {
    asm volatile("ldmatrix.sync.aligned.m8n8.x4.shared.b16 {%0,%1,%2,%3}, [%4];"
                 : "=r"(r[0]), "=r"(r[1]), "=r"(r[2]), "=r"(r[3]) : "r"(saddr));
}
__device__ __forceinline__ void ldsm_x4_t(unsigned (&r)[4], unsigned saddr) {
    asm volatile("ldmatrix.sync.aligned.m8n8.x4.trans.shared.b16 {%0,%1,%2,%3}, [%4];"
                 : "=r"(r[0]), "=r"(r[1]), "=r"(r[2]), "=r"(r[3]) : "r"(saddr));
}
// NOTE: non-volatile — pure register op; lets ptxas schedule/pipeline MMAs.
__device__ __forceinline__ void mma_bf16(float (&c)[4], const unsigned (&a)[4],
                                         unsigned b0, unsigned b1) {
    asm("mma.sync.aligned.m16n8k16.row.col.f32.bf16.bf16.f32 "
        "{%0,%1,%2,%3}, {%4,%5,%6,%7}, {%8,%9}, {%0,%1,%2,%3};"
        : "+f"(c[0]), "+f"(c[1]), "+f"(c[2]), "+f"(c[3])
        : "r"(a[0]), "r"(a[1]), "r"(a[2]), "r"(a[3]), "r"(b0), "r"(b1));
}
__device__ __forceinline__ void cp16(unsigned dst, const void* src, bool valid) {
    int sz = valid ? 16 : 0;
    asm volatile("cp.async.cg.shared.global [%0], [%1], 16, %2;"
                 :: "r"(dst), "l"(src), "r"(sz));
}
#define CP_COMMIT() asm volatile("cp.async.commit_group;")
#define CP_WAIT(n) asm volatile("cp.async.wait_group %0;" :: "n"(n))

__device__ __forceinline__ unsigned swA(int r, int c) {
    return (unsigned)(r * 64) + ((unsigned)(c ^ ((r >> 1) & 3)) << 4);
}

// ---------------------------------------------------------------------------
// Ranged split-convert (3 launches so fused_proj is the 4th kernel).
// ---------------------------------------------------------------------------
__global__ __launch_bounds__(256) void cvt_range_kernel(
    const float* __restrict__ x, const float* __restrict__ Wq,
    const float* __restrict__ Wk, const float* __restrict__ Wv,
    const float* __restrict__ Wc, const float* __restrict__ Wo,
    long long lo_i, long long hi_i) {
    long long i = lo_i + (long long)blockIdx.x * 256 + threadIdx.x;
    if (i >= hi_i) return;
    const float* src;
    __nv_bfloat16 *hi, *lo;
    long long off;
    if (i < 524288)       { src = x;  hi = g_xh;  lo = g_xl;  off = i; }
    else if (i < 2621440) { src = Wq; hi = g_Wqh; lo = g_Wql; off = i - 524288; }
    else if (i < 2752512) { src = Wk; hi = g_Wkh; lo = g_Wkl; off = i - 2621440; }
    else if (i < 2883584) { src = Wv; hi = g_Wvh; lo = g_Wvl; off = i - 2752512; }
    else if (i < 2932736) { src = Wc; hi = g_Wch; lo = g_Wcl; off = i - 2883584; }
    else if (i < 5029888) { src = Wo; hi = g_Woh; lo = g_Wol; off = i - 2932736; }
    else return;
    float4 v = ((const float4*)src)[off];
    __nv_bfloat16 h0 = __float2bfloat16(v.x), h1 = __float2bfloat16(v.y);
    __nv_bfloat16 h2 = __float2bfloat16(v.z), h3 = __float2bfloat16(v.w);
    __nv_bfloat162 a, b;
    a.x = h0; a.y = h1; b.x = h2; b.y = h3;
    ((__nv_bfloat162*)hi)[off * 2] = a;
    ((__nv_bfloat162*)hi)[off * 2 + 1] = b;
    a.x = __float2bfloat16(v.x - __bfloat162float(h0));
    a.y = __float2bfloat16(v.y - __bfloat162float(h1));
    b.x = __float2bfloat16(v.z - __bfloat162float(h2));
    b.y = __float2bfloat16(v.w - __bfloat162float(h3));
    ((__nv_bfloat162*)lo)[off * 2] = a;
    ((__nv_bfloat162*)lo)[off * 2 + 1] = b;
}

__global__ __launch_bounds__(256) void cvt_ocomb_kernel() {
    int i = blockIdx.x * 256 + threadIdx.x;
    if (i >= S_ * H_ * DV_ / 4) return;
    float4 v = ((const float4*)g_ocomb)[i];
    __nv_bfloat16 h0 = __float2bfloat16(v.x), h1 = __float2bfloat16(v.y);
    __nv_bfloat16 h2 = __float2bfloat16(v.z), h3 = __float2bfloat16(v.w);
    __nv_bfloat162 a, b;
    a.x = h0; a.y = h1; b.x = h2; b.y = h3;
    ((__nv_bfloat162*)g_oh)[i * 2] = a;
    ((__nv_bfloat162*)g_oh)[i * 2 + 1] = b;
    a.x = __float2bfloat16(v.x - __bfloat162float(h0));
    a.y = __float2bfloat16(v.y - __bfloat162float(h1));
    b.x = __float2bfloat16(v.z - __bfloat162float(h2));
    b.y = __float2bfloat16(v.w - __bfloat162float(h3));
    ((__nv_bfloat162*)g_ol)[i * 2] = a;
    ((__nv_bfloat162*)g_ol)[i * 2 + 1] = b;
}

// ---------------------------------------------------------------------------
// cp.async double-buffered MMA GEMM, term-major mma issue (16 independent
// accumulators between same-accumulator reuses).
// ---------------------------------------------------------------------------
__device__ __forceinline__ void gemm_tile_async(
    const __nv_bfloat16* __restrict__ Agh, const __nv_bfloat16* __restrict__ Agl,
    int lda,
    const __nv_bfloat16* __restrict__ Bgh, const __nv_bfloat16* __restrict__ Bgl,
    int ldb,
    float* __restrict__ Cp, int ldc,
    int K, int Nloc, int bm, int bn, char* dynsm) {
    const int tid = threadIdx.x;
    const int lane = tid & 31;
    const int w = tid >> 5;
    const int wm = (w >> 1) * 32;
    const int wn = (w & 1) * 64;

    const int ar0 = tid >> 2, ac0 = tid & 3;
    const int ar1 = ar0 + 64;
    const int br0 = tid >> 4, bc0 = tid & 15;
    const int br1 = br0 + 16;
    const bool bok = (bn + bc0 * 8 + 7) < Nloc;

    const unsigned sbase = (unsigned)__cvta_generic_to_shared(dynsm);

    float c[2][8][4];
#pragma unroll
    for (int i = 0; i < 2; i++)
#pragma unroll
        for (int j = 0; j < 8; j++)
#pragma unroll
            for (int q = 0; q < 4; q++) c[i][j][q] = 0.f;

    auto issue = [&](int step, int stage) {
        const unsigned base = sbase + stage * STAGE_BYTES;
        const int k0 = step * 32;
        cp16(base + swA(ar0, ac0), Agh + (size_t)(bm + ar0) * lda + k0 + ac0 * 8, true);
        cp16(base + swA(ar1, ac0), Agh + (size_t)(bm + ar1) * lda + k0 + ac0 * 8, true);
        cp16(base + OFF_AL + swA(ar0, ac0), Agl + (size_t)(bm + ar0) * lda + k0 + ac0 * 8, true);
        cp16(base + OFF_AL + swA(ar1, ac0), Agl + (size_t)(bm + ar1) * lda + k0 + ac0 * 8, true);
        const __nv_bfloat16* b0 = bok ? Bgh + (size_t)(k0 + br0) * ldb + bn + bc0 * 8 : Bgh;
        const __nv_bfloat16* b1 = bok ? Bgh + (size_t)(k0 + br1) * ldb + bn + bc0 * 8 : Bgh;
        const __nv_bfloat16* b2 = bok ? Bgl + (size_t)(k0 + br0) * ldb + bn + bc0 * 8 : Bgl;
        const __nv_bfloat16* b3 = bok ? Bgl + (size_t)(k0 + br1) * ldb + bn + bc0 * 8 : Bgl;
        cp16(base + OFF_BH + br0 * 272 + bc0 * 16, b0, bok);
        cp16(base + OFF_BH + br1 * 272 + bc0 * 16, b1, bok);
        cp16(base + OFF_BL + br0 * 272 + bc0 * 16, b2, bok);
        cp16(base + OFF_BL + br1 * 272 + bc0 * 16, b3, bok);
    };

    const int nSteps = K >> 5;
    issue(0, 0);
    CP_COMMIT();

    for (int step = 0; step < nSteps; step++) {
        const int cur = step & 1;
        if (step + 1 < nSteps) {
            issue(step + 1, cur ^ 1);
            CP_COMMIT();
            CP_WAIT(1);
        } else {
            CP_WAIT(0);
        }
        __syncthreads();

        const unsigned base = sbase + cur * STAGE_BYTES;
#pragma unroll
        for (int kk = 0; kk < 2; kk++) {
            unsigned ah[2][4], al[2][4], bh[4][4], bl[4][4];
#pragma unroll
            for (int i = 0; i < 2; i++) {
                int arow = wm + 16 * i + (lane & 15);
                int achunk = kk * 2 + (lane >> 4);
                unsigned off = swA(arow, achunk);
                ldsm_x4(ah[i], base + off);
                ldsm_x4(al[i], base + OFF_AL + off);
            }
#pragma unroll
            for (int j = 0; j < 4; j++) {
                unsigned brow = kk * 16 + (lane & 15);
                unsigned bcol = wn + 16 * j + 8 * (lane >> 4);
                unsigned off = brow * 272 + bcol * 2;
                ldsm_x4_t(bh[j], base + OFF_BH + off);
                ldsm_x4_t(bl[j], base + OFF_BL + off);
            }
            // term-major: 16 independent accumulators between reuses
#pragma unroll
            for (int i = 0; i < 2; i++)
#pragma unroll
                for (int jn = 0; jn < 8; jn++)
                    mma_bf16(c[i][jn], ah[i], bh[jn >> 1][(jn & 1) * 2],
                             bh[jn >> 1][(jn & 1) * 2 + 1]);
#pragma unroll
            for (int i = 0; i < 2; i++)
#pragma unroll
                for (int jn = 0; jn < 8; jn++)
                    mma_bf16(c[i][jn], ah[i], bl[jn >> 1][(jn & 1) * 2],
                             bl[jn >> 1][(jn & 1) * 2 + 1]);
#pragma unroll
            for (int i = 0; i < 2; i++)
#pragma unroll
                for (int jn = 0; jn < 8; jn++)
                    mma_bf16(c[i][jn], al[i], bh[jn >> 1][(jn & 1) * 2],
                             bh[jn >> 1][(jn & 1) * 2 + 1]);
        }
        __syncthreads();
    }

    const int qrow = lane >> 2;
    const int qcol = (lane & 3) * 2;
#pragma unroll
    for (int i = 0; i < 2; i++) {
        const int row0 = bm + wm + 16 * i + qrow;
#pragma unroll
        for (int jn = 0; jn < 8; jn++) {
            const int col = bn + wn + jn * 8 + qcol;
            if (col < Nloc) {
                *(float2*)&Cp[(size_t)row0 * ldc + col] =
                    make_float2(c[i][jn][0], c[i][jn][1]);
                *(float2*)&Cp[(size_t)(row0 + 8) * ldc + col] =
                    make_float2(c[i][jn][2], c[i][jn][3]);
            }
        }
    }
}

__global__ __launch_bounds__(256) void fused_proj_mma(
    float* __restrict__ qraw, float* __restrict__ kraw,
    float* __restrict__ v, float* __restrict__ gates) {
    extern __shared__ char dynsm[];
    const int t = blockIdx.x;
    const int bm = blockIdx.y * 128;
    const __nv_bfloat16 *Bh, *Bl;
    float* Cp;
    int Nloc, bn;
    if (t < 32)      { Bh = g_Wqh; Bl = g_Wql; Cp = qraw;  Nloc = NQ_;  bn = t * 128; }
    else if (t < 34) { Bh = g_Wkh; Bl = g_Wkl; Cp = kraw;  Nloc = NKV_; bn = (t - 32) * 128; }
    else if (t < 36) { Bh = g_Wvh; Bl = g_Wvl; Cp = v;     Nloc = NKV_; bn = (t - 34) * 128; }
    else             { Bh = g_Wch; Bl = g_Wcl; Cp = gates; Nloc = NC_;  bn = 0; }
    gemm_tile_async(g_xh, g_xl, D_, Bh, Bl, Nloc, Cp, Nloc, D_, Nloc, bm, bn, dynsm);
}

__global__ __launch_bounds__(256) void gemm_out_mma(float* __restrict__ out) {
    extern __shared__ char dynsm[];
    gemm_tile_async(g_oh, g_ol, H_ * DV_, g_Woh, g_Wol, D_, out, D_,
                    H_ * DV_, D_, blockIdx.y * 128, blockIdx.x * 128, dynsm);
}

// ---------------------------------------------------------------------------
// Fused elementwise: RoPE(q), RoPE(k), sigmoid(gates).
// ---------------------------------------------------------------------------
__global__ __launch_bounds__(256) void ew_all_kernel(const float* __restrict__ cosp,
                                                     const float* __restrict__ sinp) {
    int i = blockIdx.x * 256 + threadIdx.x;
    if (i < S_ * NQ_) {
        int d = i & 127;
        int s = i >> 12;
        float c = cosp[s * DQ_ + d], sn = sinp[s * DQ_ + d];
        float t = g_qraw[i];
        float rot = (d < 64) ? -g_qraw[i + 64] : g_qraw[i - 64];
        g_q[i] = t * c + rot * sn;
        return;
    }
    i -= S_ * NQ_;
    if (i < S_ * NKV_) {
        int d = i & 127;
        int s = i >> 8;
        float c = cosp[s * DQ_ + d], sn = sinp[s * DQ_ + d];
        float t = g_kraw[i];
        float rot = (d < 64) ? -g_kraw[i + 64] : g_kraw[i - 64];
        g_k[i] = t * c + rot * sn;
        return;
    }
    i -= S_ * NKV_;
    if (i < S_ * NC_) {
        g_gates[i] = 1.f / (1.f + expf(-g_gates[i]));
    }
}

__global__ __launch_bounds__(256) void kcvc_kernel() {
    int i = blockIdx.x * 256 + threadIdx.x;
    if (i >= C_ * G_ * DQ_) return;
    int d = i & 127;
    int g = (i >> 7) & 1;
    int c = i >> 8;
    float sk = 0.f, sv = 0.f;
    for (int j = 0; j < BLK_; j++) {
        int t = c * BLK_ + j;
        sk += g_k[(t * G_ + g) * DQ_ + d];
        sv += g_v[(t * G_ + g) * DV_ + d];
    }
    g_kc[i] = sk * (1.f / 64.f);
    g_vc[i] = sv * (1.f / 64.f);
}

// ---------------------------------------------------------------------------
// Compressed attention + importance + stable top-4 selection (proven).
// ---------------------------------------------------------------------------
__global__ __launch_bounds__(512) void cmp_attn_kernel() {
    const int s = blockIdx.x;
    const int g = blockIdx.y;
    __shared__ float kcs[C_][DQ_];
    __shared__ float vcs[C_][DQ_];
    __shared__ float pw[HG_][C_];
    const int tid = threadIdx.x;

    for (int i = tid; i < C_ * DQ_; i += 512) {
        int c = i >> 7, d = i & 127;
        kcs[c][d] = g_kc[(c * G_ + g) * DQ_ + d];
        vcs[c][d] = g_vc[(c * G_ + g) * DV_ + d];
    }
    __syncthreads();

    const int w = tid >> 5, l = tid & 31;
    const int h = g * HG_ + w;
    const float* qp = &g_q[(s * H_ + h) * DQ_];
    float q0 = qp[l], q1 = qp[l + 32], q2 = qp[l + 64], q3 = qp[l + 96];

    const int ncmp = (s + 1) >> 6;
    float logit[C_];
#pragma unroll
    for (int c = 0; c < C_; c++) {
        if (c < ncmp) {
            float part = q0 * kcs[c][l] + q1 * kcs[c][l + 32] +
                         q2 * kcs[c][l + 64] + q3 * kcs[c][l + 96];
            logit[c] = warp_sum(part) * SCALE_;
        } else {
            logit[c] = -1e30f;
        }
    }
    float m = -1e30f;
#pragma unroll
    for (int c = 0; c < C_; c++) m = fmaxf(m, logit[c]);
    float p[C_];
    float sum = 0.f;
#pragma unroll
    for (int c = 0; c < C_; c++) {
        float e = (logit[c] > -1e29f) ? expf(logit[c] - m) : 0.f;
        p[c] = e;
        sum += e;
    }
    float inv = (sum > 0.f) ? 1.f / sum : 0.f;

    float o0 = 0.f, o1 = 0.f, o2 = 0.f, o3 = 0.f;
#pragma unroll
    for (int c = 0; c < C_; c++) {
        float pc = p[c] * inv;
        o0 += pc * vcs[c][l];
        o1 += pc * vcs[c][l + 32];
        o2 += pc * vcs[c][l + 64];
        o3 += pc * vcs[c][l + 96];
        if (l == 0) pw[w][c] = pc;
    }
    float gate = g_gates[(s * H_ + h) * 3 + 0];
    float* op = &g_ocomb[(s * H_ + h) * DV_];
    op[l]      = gate * o0;
    op[l + 32] = gate * o1;
    op[l + 64] = gate * o2;
    op[l + 96] = gate * o3;
    __syncthreads();

    if (tid == 0) {
        const int cur = s >> 6;
        float imp[C_];
        for (int c = 0; c < C_; c++) {
            float v;
            if (c > cur) v = -1e9f;
            else if (c == 0 || c == cur) v = 1e9f;
            else {
                v = 0.f;
                for (int ww = 0; ww < HG_; ww++) v += pw[ww][c];
            }
            imp[c] = v;
        }
        bool tk[C_];
        for (int c = 0; c < C_; c++) tk[c] = false;
        for (int t = 0; t < TOPN_; t++) {
            float best = -3e38f;
            int bi = 0;
            for (int c = 0; c < C_; c++)
                if (!tk[c] && imp[c] > best) { best = imp[c]; bi = c; }
            tk[bi] = true;
            g_idx[(s * G_ + g) * TOPN_ + t] = bi;
        }
    }
}

// ---------------------------------------------------------------------------
// Fused selected + window attention (proven R5 layout).
// ---------------------------------------------------------------------------
struct SlcWinSmem {
    float kv[BLK_][132];
    float qsh[HG_][DQ_];
    int idxs[TOPN_];
};

__device__ __forceinline__ void stage_kv(SlcWinSmem& sm, const float* __restrict__ src,
                                         int t0, int g, int tid) {
    for (int i = tid; i < BLK_ * 32; i += 512) {
        int j = i >> 5, d4 = i & 31;
        float4 v = *(const float4*)&src[((t0 + j) * G_ + g) * DQ_ + d4 * 4];
        *(float4*)&sm.kv[j][d4 * 4] = v;
    }
}

__device__ __forceinline__ void qk_block(const SlcWinSmem& sm, int w, int l,
                                         float& a0, float& a1) {
    a0 = 0.f; a1 = 0.f;
#pragma unroll
    for (int d4 = 0; d4 < 32; d4++) {
        float4 qv = *(const float4*)&sm.qsh[w][d4 * 4];
        float4 k0 = *(const float4*)&sm.kv[l][d4 * 4];
        float4 k1 = *(const float4*)&sm.kv[l + 32][d4 * 4];
        a0 += qv.x * k0.x + qv.y * k0.y + qv.z * k0.z + qv.w * k0.w;
        a1 += qv.x * k1.x + qv.y * k1.y + qv.z * k1.z + qv.w * k1.w;
    }
}

__device__ __forceinline__ void pv_block(const SlcWinSmem& sm, int l,
                                         float p0reg, float p1reg,
                                         float& o0, float& o1, float& o2, float& o3) {
#pragma unroll 8
    for (int j = 0; j < BLK_; j++) {
        float pj = __shfl_sync(0xffffffffu, (j < 32) ? p0reg : p1reg, j & 31);
        o0 += pj * sm.kv[j][l];
        o1 += pj * sm.kv[j][l + 32];
        o2 += pj * sm.kv[j][l + 64];
        o3 += pj * sm.kv[j][l + 96];
    }
}

__global__ __launch_bounds__(512) void slcwin_attn_kernel() {
    const int s = blockIdx.x, g = blockIdx.y;
    __shared__ SlcWinSmem sm;
    const int tid = threadIdx.x;
    const int w = tid >> 5, l = tid & 31;

    for (int i = tid; i < HG_ * 32; i += 512) {
        int hh = i >> 5, d4 = i & 31;
        *(float4*)&sm.qsh[hh][d4 * 4] =
            *(const float4*)&g_q[(s * H_ + g * HG_ + hh) * DQ_ + d4 * 4];
    }
    if (tid < TOPN_) sm.idxs[tid] = g_idx[(s * G_ + g) * TOPN_ + tid];
    __syncthreads();

    int blk[TOPN_];
#pragma unroll
    for (int n = 0; n < TOPN_; n++) blk[n] = sm.idxs[n];

    float ls[8];
    float oS0 = 0.f, oS1 = 0.f, oS2 = 0.f, oS3 = 0.f;

    // selected branch
#pragma unroll
    for (int n = 0; n < TOPN_; n++) {
        const int t0 = blk[n] * BLK_;
        stage_kv(sm, g_k, t0, g, tid);
        __syncthreads();
        float a0, a1;
        qk_block(sm, w, l, a0, a1);
        ls[n * 2 + 0] = (t0 + l <= s) ? a0 * SCALE_ : -1e30f;
        ls[n * 2 + 1] = (t0 + l + 32 <= s) ? a1 * SCALE_ : -1e30f;
        __syncthreads();
    }
    {
        float m = -1e30f;
#pragma unroll
        for (int r = 0; r < 8; r++) m = fmaxf(m, ls[r]);
        m = warp_max(m);
        float sum = 0.f;
#pragma unroll
        for (int r = 0; r < 8; r++) {
            ls[r] = (ls[r] > -1e29f) ? expf(ls[r] - m) : 0.f;
            sum += ls[r];
        }
        sum = warp_sum(sum);
        float inv = 1.f / sum;
#pragma unroll
        for (int r = 0; r < 8; r++) ls[r] *= inv;
    }
#pragma unroll
    for (int n = 0; n < TOPN_; n++) {
        stage_kv(sm, g_v, blk[n] * BLK_, g, tid);
        __syncthreads();
        pv_block(sm, l, ls[n * 2], ls[n * 2 + 1], oS0, oS1, oS2, oS3);
        __syncthreads();
    }

    // window branch
    const int wstart = (s >= WIN_) ? (s - WIN_ + 1) : 0;
    float oW0 = 0.f, oW1 = 0.f, oW2 = 0.f, oW3 = 0.f;
#pragma unroll
    for (int n = 0; n < 4; n++) {
        const int t0 = wstart + n * BLK_;
        stage_kv(sm, g_k, t0, g, tid);
        __syncthreads();
        float a0, a1;
        qk_block(sm, w, l, a0, a1);
        ls[n * 2 + 0] = (t0 + l <= s) ? a0 * SCALE_ : -1e30f;
        ls[n * 2 + 1] = (t0 + l + 32 <= s) ? a1 * SCALE_ : -1e30f;
        __syncthreads();
    }
    {
        float m = -1e30f;
#pragma unroll
        for (int r = 0; r < 8; r++) m = fmaxf(m, ls[r]);
        m = warp_max(m);
        float sum = 0.f;
#pragma unroll
        for (int r = 0; r < 8; r++) {
            ls[r] = (ls[r] > -1e29f) ? expf(ls[r] - m) : 0.f;
            sum += ls[r];
        }
        sum = warp_sum(sum);
        float inv = 1.f / sum;
#pragma unroll
        for (int r = 0; r < 8; r++) ls[r] *= inv;
    }
#pragma unroll
    for (int n = 0; n < 4; n++) {
        stage_kv(sm, g_v, wstart + n * BLK_, g, tid);
        __syncthreads();
        pv_block(sm, l, ls[n * 2], ls[n * 2 + 1], oW0, oW1, oW2, oW3);
        __syncthreads();
    }

    const int h = g * HG_ + w;
    float g1 = g_gates[(s * H_ + h) * 3 + 1];
    float g2 = g_gates[(s * H_ + h) * 3 + 2];
    float* op = &g_ocomb[(s * H_ + h) * DV_];
    op[l]      += g1 * oS0 + g2 * oW0;
    op[l + 32] += g1 * oS1 + g2 * oW1;
    op[l + 64] += g1 * oS2 + g2 * oW2;
    op[l + 96] += g1 * oS3 + g2 * oW3;
}

// ---------------------------------------------------------------------------
extern "C" void kernel_launch(void* const* d_in, const int* in_sizes, int n_in,
                              void* d_out, int out_size) {
    const float* x    = (const float*)d_in[0];
    const float* cosp = (const float*)d_in[1];
    const float* sinp = (const float*)d_in[2];
    const float* Wq   = (const float*)d_in[3];
    const float* Wk   = (const float*)d_in[4];
    const float* Wv   = (const float*)d_in[5];
    const float* Wo   = (const float*)d_in[6];
    const float* Wc   = (const float*)d_in[7];
    float* out = (float*)d_out;

    float *p_qraw, *p_kraw, *p_v, *p_gates;
    cudaGetSymbolAddress((void**)&p_qraw, g_qraw);
    cudaGetSymbolAddress((void**)&p_kraw, g_kraw);
    cudaGetSymbolAddress((void**)&p_v, g_v);
    cudaGetSymbolAddress((void**)&p_gates, g_gates);

    cudaFuncSetAttribute(fused_proj_mma,
                         cudaFuncAttributeMaxDynamicSharedMemorySize, GEMM_SMEM);
    cudaFuncSetAttribute(gemm_out_mma,
                         cudaFuncAttributeMaxDynamicSharedMemorySize, GEMM_SMEM);

    // split conversions as 3 launches -> fused_proj_mma is launch #4 (ncu slot)
    auto cvt_range = [&](long long lo, long long hi) {
        long long n = hi - lo;
        cvt_range_kernel<<<(unsigned)((n + 255) / 256), 256>>>(x, Wq, Wk, Wv, Wc, Wo,
                                                               lo, hi);
    };
    cvt_range(0, 524288);           // x
    cvt_range(524288, 2932736);     // Wq, Wk, Wv, Wc
    cvt_range(2932736, 5029888);    // Wo

    // fused projections: 37 n-tiles x 8 m-tiles  (launch #4 — profiled)
    fused_proj_mma<<<dim3(37, 8), 256, GEMM_SMEM>>>(p_qraw, p_kraw, p_v, p_gates);

    // fused elementwise (rope q, rope k, sigmoid) + block means
    ew_all_kernel<<<(S_ * NQ_ + S_ * NKV_ + S_ * NC_ + 255) / 256, 256>>>(cosp, sinp);
    kcvc_kernel<<<(C_ * G_ * DQ_ + 255) / 256, 256>>>();

    // attention
    cmp_attn_kernel<<<dim3(S_, G_), 512>>>();
    slcwin_attn_kernel<<<dim3(S_, G_), 512>>>();

    // split ocomb, output projection
    cvt_ocomb_kernel<<<(S_ * H_ * DV_ / 4 + 255) / 256, 256>>>();
    gemm_out_mma<<<dim3(16, 8), 256, GEMM_SMEM>>>(out);
}

// round 16
// speedup vs baseline: 1.4703x; 1.2392x over previous
#include <cuda_runtime.h>
#include <cuda_bf16.h>

// ---------------------------------------------------------------------------
// NSA forward. R9: fused attention kernel (cmp + top-k + slc + win) with
// 8 warps x 2 heads, f32x2 packed FMA, lane-per-block cmp logits.
// GEMMs unchanged (R8, 65.8% tensor pipe). kcvc folded into ew_all so the
// fused attention kernel is launch #4 (the ncu capture slot).
// ---------------------------------------------------------------------------

namespace {
constexpr int S_ = 1024;
constexpr int D_ = 2048;
constexpr int H_ = 32;
constexpr int G_ = 2;
constexpr int HG_ = 16;
constexpr int DQ_ = 128;
constexpr int DV_ = 128;
constexpr int BLK_ = 64;
constexpr int C_ = 16;
constexpr int TOPN_ = 4;
constexpr int WIN_ = 256;
constexpr int NQ_ = H_ * DQ_;   // 4096
constexpr int NKV_ = G_ * DQ_;  // 256
constexpr int NC_ = H_ * 3;     // 96
constexpr float SCALE_ = 0.08838834764831845f;

constexpr unsigned OFF_AL = 8192;
constexpr unsigned OFF_BH = 16384;
constexpr unsigned OFF_BL = 25088;
constexpr unsigned STAGE_BYTES = 33792;
constexpr unsigned GEMM_SMEM = 2 * STAGE_BYTES;  // 67584
}

typedef unsigned long long ull;

// fp32 scratch
__device__ float g_qraw[S_ * NQ_];
__device__ float g_q[S_ * NQ_];
__device__ float g_kraw[S_ * NKV_];
__device__ float g_k[S_ * NKV_];
__device__ float g_v[S_ * NKV_];
__device__ float g_gates[S_ * NC_];
__device__ float g_kc[C_ * G_ * DQ_];
__device__ float g_vc[C_ * G_ * DV_];
__device__ float g_ocomb[S_ * H_ * DV_];

// bf16 split planes
__device__ __align__(16) __nv_bfloat16 g_xh[S_ * D_],  g_xl[S_ * D_];
__device__ __align__(16) __nv_bfloat16 g_Wqh[D_ * NQ_], g_Wql[D_ * NQ_];
__device__ __align__(16) __nv_bfloat16 g_Wkh[D_ * NKV_], g_Wkl[D_ * NKV_];
__device__ __align__(16) __nv_bfloat16 g_Wvh[D_ * NKV_], g_Wvl[D_ * NKV_];
__device__ __align__(16) __nv_bfloat16 g_Wch[D_ * NC_],  g_Wcl[D_ * NC_];
__device__ __align__(16) __nv_bfloat16 g_Woh[H_ * DV_ * D_], g_Wol[H_ * DV_ * D_];
__device__ __align__(16) __nv_bfloat16 g_oh[S_ * H_ * DV_], g_ol[S_ * H_ * DV_];

__device__ __forceinline__ float warp_sum(float v) {
#pragma unroll
    for (int o = 16; o > 0; o >>= 1) v += __shfl_xor_sync(0xffffffffu, v, o);
    return v;
}
__device__ __forceinline__ float warp_max(float v) {
#pragma unroll
    for (int o = 16; o > 0; o >>= 1) v = fmaxf(v, __shfl_xor_sync(0xffffffffu, v, o));
    return v;
}

// ---- f32x2 helpers ---------------------------------------------------------
__device__ __forceinline__ ull d_dup(float v) {
    ull r;
    asm("mov.b64 %0, {%1, %1};" : "=l"(r) : "f"(v));
    return r;
}
__device__ __forceinline__ float2 d_unpack(ull p) {
    float lo, hi;
    asm("mov.b64 {%0, %1}, %2;" : "=f"(lo), "=f"(hi) : "l"(p));
    return make_float2(lo, hi);
}
__device__ __forceinline__ void d_fma2(ull& d, ull a, ull b) {
    asm("fma.rn.f32x2 %0, %1, %2, %0;" : "+l"(d) : "l"(a), "l"(b));
}
__device__ __forceinline__ float d_pairsum(ull p) {
    float2 u = d_unpack(p);
    return u.x + u.y;
}

// ---- tensor-core / async primitives ---------------------------------------
__device__ __forceinline__ void ldsm_x4(unsigned (&r)[4], unsigned saddr) {
    asm volatile("ldmatrix.sync.aligned.m8n8.x4.shared.b16 {%0,%1,%2,%3}, [%4];"
                 : "=r"(r[0]), "=r"(r[1]), "=r"(r[2]), "=r"(r[3]) : "r"(saddr));
}
__device__ __forceinline__ void ldsm_x4_t(unsigned (&r)[4], unsigned saddr) {
    asm volatile("ldmatrix.sync.aligned.m8n8.x4.trans.shared.b16 {%0,%1,%2,%3}, [%4];"
                 : "=r"(r[0]), "=r"(r[1]), "=r"(r[2]), "=r"(r[3]) : "r"(saddr));
}
__device__ __forceinline__ void mma_bf16(float (&c)[4], const unsigned (&a)[4],
                                         unsigned b0, unsigned b1) {
    asm("mma.sync.aligned.m16n8k16.row.col.f32.bf16.bf16.f32 "
        "{%0,%1,%2,%3}, {%4,%5,%6,%7}, {%8,%9}, {%0,%1,%2,%3};"
        : "+f"(c[0]), "+f"(c[1]), "+f"(c[2]), "+f"(c[3])
        : "r"(a[0]), "r"(a[1]), "r"(a[2]), "r"(a[3]), "r"(b0), "r"(b1));
}
__device__ __forceinline__ void cp16(unsigned dst, const void* src, bool valid) {
    int sz = valid ? 16 : 0;
    asm volatile("cp.async.cg.shared.global [%0], [%1], 16, %2;"
                 :: "r"(dst), "l"(src), "r"(sz));
}
#define CP_COMMIT() asm volatile("cp.async.commit_group;")
#define CP_WAIT(n) asm volatile("cp.async.wait_group %0;" :: "n"(n))

__device__ __forceinline__ unsigned swA(int r, int c) {
    return (unsigned)(r * 64) + ((unsigned)(c ^ ((r >> 1) & 3)) << 4);
}

// ---------------------------------------------------------------------------
// Fused split-convert (single launch)
// ---------------------------------------------------------------------------
__global__ __launch_bounds__(256) void cvt_all_kernel(
    const float* __restrict__ x, const float* __restrict__ Wq,
    const float* __restrict__ Wk, const float* __restrict__ Wv,
    const float* __restrict__ Wc, const float* __restrict__ Wo) {
    long long i = (long long)blockIdx.x * 256 + threadIdx.x;
    const float* src;
    __nv_bfloat16 *hi, *lo;
    long long off;
    if (i < 524288)       { src = x;  hi = g_xh;  lo = g_xl;  off = i; }
    else if (i < 2621440) { src = Wq; hi = g_Wqh; lo = g_Wql; off = i - 524288; }
    else if (i < 2752512) { src = Wk; hi = g_Wkh; lo = g_Wkl; off = i - 2621440; }
    else if (i < 2883584) { src = Wv; hi = g_Wvh; lo = g_Wvl; off = i - 2752512; }
    else if (i < 2932736) { src = Wc; hi = g_Wch; lo = g_Wcl; off = i - 2883584; }
    else if (i < 5029888) { src = Wo; hi = g_Woh; lo = g_Wol; off = i - 2932736; }
    else return;
    float4 v = ((const float4*)src)[off];
    __nv_bfloat16 h0 = __float2bfloat16(v.x), h1 = __float2bfloat16(v.y);
    __nv_bfloat16 h2 = __float2bfloat16(v.z), h3 = __float2bfloat16(v.w);
    __nv_bfloat162 a, b;
    a.x = h0; a.y = h1; b.x = h2; b.y = h3;
    ((__nv_bfloat162*)hi)[off * 2] = a;
    ((__nv_bfloat162*)hi)[off * 2 + 1] = b;
    a.x = __float2bfloat16(v.x - __bfloat162float(h0));
    a.y = __float2bfloat16(v.y - __bfloat162float(h1));
    b.x = __float2bfloat16(v.z - __bfloat162float(h2));
    b.y = __float2bfloat16(v.w - __bfloat162float(h3));
    ((__nv_bfloat162*)lo)[off * 2] = a;
    ((__nv_bfloat162*)lo)[off * 2 + 1] = b;
}

__global__ __launch_bounds__(256) void cvt_ocomb_kernel() {
    int i = blockIdx.x * 256 + threadIdx.x;
    if (i >= S_ * H_ * DV_ / 4) return;
    float4 v = ((const float4*)g_ocomb)[i];
    __nv_bfloat16 h0 = __float2bfloat16(v.x), h1 = __float2bfloat16(v.y);
    __nv_bfloat16 h2 = __float2bfloat16(v.z), h3 = __float2bfloat16(v.w);
    __nv_bfloat162 a, b;
    a.x = h0; a.y = h1; b.x = h2; b.y = h3;
    ((__nv_bfloat162*)g_oh)[i * 2] = a;
    ((__nv_bfloat162*)g_oh)[i * 2 + 1] = b;
    a.x = __float2bfloat16(v.x - __bfloat162float(h0));
    a.y = __float2bfloat16(v.y - __bfloat162float(h1));
    b.x = __float2bfloat16(v.z - __bfloat162float(h2));
    b.y = __float2bfloat16(v.w - __bfloat162float(h3));
    ((__nv_bfloat162*)g_ol)[i * 2] = a;
    ((__nv_bfloat162*)g_ol)[i * 2 + 1] = b;
}

// ---------------------------------------------------------------------------
// cp.async double-buffered MMA GEMM (R8 proven, 65.8% tensor pipe).
// ---------------------------------------------------------------------------
__device__ __forceinline__ void gemm_tile_async(
    const __nv_bfloat16* __restrict__ Agh, const __nv_bfloat16* __restrict__ Agl,
    int lda,
    const __nv_bfloat16* __restrict__ Bgh, const __nv_bfloat16* __restrict__ Bgl,
    int ldb,
    float* __restrict__ Cp, int ldc,
    int K, int Nloc, int bm, int bn, char* dynsm) {
    const int tid = threadIdx.x;
    const int lane = tid & 31;
    const int w = tid >> 5;
    const int wm = (w >> 1) * 32;
    const int wn = (w & 1) * 64;

    const int ar0 = tid >> 2, ac0 = tid & 3;
    const int ar1 = ar0 + 64;
    const int br0 = tid >> 4, bc0 = tid & 15;
    const int br1 = br0 + 16;
    const bool bok = (bn + bc0 * 8 + 7) < Nloc;

    const unsigned sbase = (unsigned)__cvta_generic_to_shared(dynsm);

    float c[2][8][4];
#pragma unroll
    for (int i = 0; i < 2; i++)
#pragma unroll
        for (int j = 0; j < 8; j++)
#pragma unroll
            for (int q = 0; q < 4; q++) c[i][j][q] = 0.f;

    auto issue = [&](int step, int stage) {
        const unsigned base = sbase + stage * STAGE_BYTES;
        const int k0 = step * 32;
        cp16(base + swA(ar0, ac0), Agh + (size_t)(bm + ar0) * lda + k0 + ac0 * 8, true);
        cp16(base + swA(ar1, ac0), Agh + (size_t)(bm + ar1) * lda + k0 + ac0 * 8, true);
        cp16(base + OFF_AL + swA(ar0, ac0), Agl + (size_t)(bm + ar0) * lda + k0 + ac0 * 8, true);
        cp16(base + OFF_AL + swA(ar1, ac0), Agl + (size_t)(bm + ar1) * lda + k0 + ac0 * 8, true);
        const __nv_bfloat16* b0 = bok ? Bgh + (size_t)(k0 + br0) * ldb + bn + bc0 * 8 : Bgh;
        const __nv_bfloat16* b1 = bok ? Bgh + (size_t)(k0 + br1) * ldb + bn + bc0 * 8 : Bgh;
        const __nv_bfloat16* b2 = bok ? Bgl + (size_t)(k0 + br0) * ldb + bn + bc0 * 8 : Bgl;
        const __nv_bfloat16* b3 = bok ? Bgl + (size_t)(k0 + br1) * ldb + bn + bc0 * 8 : Bgl;
        cp16(base + OFF_BH + br0 * 272 + bc0 * 16, b0, bok);
        cp16(base + OFF_BH + br1 * 272 + bc0 * 16, b1, bok);
        cp16(base + OFF_BL + br0 * 272 + bc0 * 16, b2, bok);
        cp16(base + OFF_BL + br1 * 272 + bc0 * 16, b3, bok);
    };

    const int nSteps = K >> 5;
    issue(0, 0);
    CP_COMMIT();

    for (int step = 0; step < nSteps; step++) {
        const int cur = step & 1;
        if (step + 1 < nSteps) {
            issue(step + 1, cur ^ 1);
            CP_COMMIT();
            CP_WAIT(1);
        } else {
            CP_WAIT(0);
        }
        __syncthreads();

        const unsigned base = sbase + cur * STAGE_BYTES;
#pragma unroll
        for (int kk = 0; kk < 2; kk++) {
            unsigned ah[2][4], al[2][4], bh[4][4], bl[4][4];
#pragma unroll
            for (int i = 0; i < 2; i++) {
                int arow = wm + 16 * i + (lane & 15);
                int achunk = kk * 2 + (lane >> 4);
                unsigned off = swA(arow, achunk);
                ldsm_x4(ah[i], base + off);
                ldsm_x4(al[i], base + OFF_AL + off);
            }
#pragma unroll
            for (int j = 0; j < 4; j++) {
                unsigned brow = kk * 16 + (lane & 15);
                unsigned bcol = wn + 16 * j + 8 * (lane >> 4);
                unsigned off = brow * 272 + bcol * 2;
                ldsm_x4_t(bh[j], base + OFF_BH + off);
                ldsm_x4_t(bl[j], base + OFF_BL + off);
            }
#pragma unroll
            for (int i = 0; i < 2; i++)
#pragma unroll
                for (int jn = 0; jn < 8; jn++)
                    mma_bf16(c[i][jn], ah[i], bh[jn >> 1][(jn & 1) * 2],
                             bh[jn >> 1][(jn & 1) * 2 + 1]);
#pragma unroll
            for (int i = 0; i < 2; i++)
#pragma unroll
                for (int jn = 0; jn < 8; jn++)
                    mma_bf16(c[i][jn], ah[i], bl[jn >> 1][(jn & 1) * 2],
                             bl[jn >> 1][(jn & 1) * 2 + 1]);
#pragma unroll
            for (int i = 0; i < 2; i++)
#pragma unroll
                for (int jn = 0; jn < 8; jn++)
                    mma_bf16(c[i][jn], al[i], bh[jn >> 1][(jn & 1) * 2],
                             bh[jn >> 1][(jn & 1) * 2 + 1]);
        }
        __syncthreads();
    }

    const int qrow = lane >> 2;
    const int qcol = (lane & 3) * 2;
#pragma unroll
    for (int i = 0; i < 2; i++) {
        const int row0 = bm + wm + 16 * i + qrow;
#pragma unroll
        for (int jn = 0; jn < 8; jn++) {
            const int col = bn + wn + jn * 8 + qcol;
            if (col < Nloc) {
                *(float2*)&Cp[(size_t)row0 * ldc + col] =
                    make_float2(c[i][jn][0], c[i][jn][1]);
                *(float2*)&Cp[(size_t)(row0 + 8) * ldc + col] =
                    make_float2(c[i][jn][2], c[i][jn][3]);
            }
        }
    }
}

__global__ __launch_bounds__(256) void fused_proj_mma(
    float* __restrict__ qraw, float* __restrict__ kraw,
    float* __restrict__ v, float* __restrict__ gates) {
    extern __shared__ char dynsm[];
    const int t = blockIdx.x;
    const int bm = blockIdx.y * 128;
    const __nv_bfloat16 *Bh, *Bl;
    float* Cp;
    int Nloc, bn;
    if (t < 32)      { Bh = g_Wqh; Bl = g_Wql; Cp = qraw;  Nloc = NQ_;  bn = t * 128; }
    else if (t < 34) { Bh = g_Wkh; Bl = g_Wkl; Cp = kraw;  Nloc = NKV_; bn = (t - 32) * 128; }
    else if (t < 36) { Bh = g_Wvh; Bl = g_Wvl; Cp = v;     Nloc = NKV_; bn = (t - 34) * 128; }
    else             { Bh = g_Wch; Bl = g_Wcl; Cp = gates; Nloc = NC_;  bn = 0; }
    gemm_tile_async(g_xh, g_xl, D_, Bh, Bl, Nloc, Cp, Nloc, D_, Nloc, bm, bn, dynsm);
}

__global__ __launch_bounds__(256) void gemm_out_mma(float* __restrict__ out) {
    extern __shared__ char dynsm[];
    gemm_tile_async(g_oh, g_ol, H_ * DV_, g_Woh, g_Wol, D_, out, D_,
                    H_ * DV_, D_, blockIdx.y * 128, blockIdx.x * 128, dynsm);
}

// ---------------------------------------------------------------------------
// Fused elementwise: RoPE(q), RoPE(k), sigmoid(gates), block means (kc/vc
// computed from kraw + cos/sin — bit-identical to rope-then-mean).
// ---------------------------------------------------------------------------
__global__ __launch_bounds__(256) void ew_all_kernel(const float* __restrict__ cosp,
                                                     const float* __restrict__ sinp) {
    int i = blockIdx.x * 256 + threadIdx.x;
    if (i < S_ * NQ_) {
        int d = i & 127;
        int s = i >> 12;
        float c = cosp[s * DQ_ + d], sn = sinp[s * DQ_ + d];
        float t = g_qraw[i];
        float rot = (d < 64) ? -g_qraw[i + 64] : g_qraw[i - 64];
        g_q[i] = t * c + rot * sn;
        return;
    }
    i -= S_ * NQ_;
    if (i < S_ * NKV_) {
        int d = i & 127;
        int s = i >> 8;
        float c = cosp[s * DQ_ + d], sn = sinp[s * DQ_ + d];
        float t = g_kraw[i];
        float rot = (d < 64) ? -g_kraw[i + 64] : g_kraw[i - 64];
        g_k[i] = t * c + rot * sn;
        return;
    }
    i -= S_ * NKV_;
    if (i < S_ * NC_) {
        g_gates[i] = 1.f / (1.f + expf(-g_gates[i]));
        return;
    }
    i -= S_ * NC_;
    if (i < C_ * G_ * DQ_) {
        int d = i & 127;
        int g = (i >> 7) & 1;
        int c = i >> 8;
        float sk = 0.f, sv = 0.f;
        for (int j = 0; j < BLK_; j++) {
            int t = c * BLK_ + j;
            float kr = g_kraw[(t * G_ + g) * DQ_ + d];
            float rot = (d < 64) ? -g_kraw[(t * G_ + g) * DQ_ + d + 64]
                                 : g_kraw[(t * G_ + g) * DQ_ + d - 64];
            sk += kr * cosp[t * DQ_ + d] + rot * sinp[t * DQ_ + d];
            sv += g_v[(t * G_ + g) * DV_ + d];
        }
        g_kc[i] = sk * (1.f / 64.f);
        g_vc[i] = sv * (1.f / 64.f);
    }
}

// ---------------------------------------------------------------------------
// Fused attention: cmp + top-4 + selected + window. One CTA per (s, g),
// 256 threads = 8 warps x 2 heads. f32x2 packed FMA throughout.
// ---------------------------------------------------------------------------
struct AttnSmem {
    union {
        float kv[BLK_][132];        // slc/win tile (33792 B)
        float cmp[2][C_][DQ_];      // [0]=kc, [1]=vc (16384 B)
    } u;
    float qsh[HG_][DQ_];
    float pw[HG_][C_];
    int idxs[TOPN_];
};

__device__ __forceinline__ void stage_kv256(AttnSmem& sm, const float* __restrict__ src,
                                            int t0, int g, int tid) {
    for (int i = tid; i < BLK_ * 32; i += 256) {
        int j = i >> 5, d4 = i & 31;
        float4 v = *(const float4*)&src[((t0 + j) * G_ + g) * DQ_ + d4 * 4];
        *(float4*)&sm.u.kv[j][d4 * 4] = v;
    }
}

// QK for one staged block: 2 heads, keys l and l+32.
__device__ __forceinline__ void qk2(const AttnSmem& sm, int h0, int h1, int l,
                                    float& a00, float& a01, float& a10, float& a11) {
    ull p00 = 0, p01 = 0, p10 = 0, p11 = 0;
#pragma unroll
    for (int d4 = 0; d4 < 32; d4++) {
        ulonglong2 k0 = *(const ulonglong2*)&sm.u.kv[l][d4 * 4];
        ulonglong2 k1 = *(const ulonglong2*)&sm.u.kv[l + 32][d4 * 4];
        ulonglong2 q0 = *(const ulonglong2*)&sm.qsh[h0][d4 * 4];
        ulonglong2 q1 = *(const ulonglong2*)&sm.qsh[h1][d4 * 4];
        d_fma2(p00, q0.x, k0.x); d_fma2(p00, q0.y, k0.y);
        d_fma2(p01, q0.x, k1.x); d_fma2(p01, q0.y, k1.y);
        d_fma2(p10, q1.x, k0.x); d_fma2(p10, q1.y, k0.y);
        d_fma2(p11, q1.x, k1.x); d_fma2(p11, q1.y, k1.y);
    }
    a00 = d_pairsum(p00); a01 = d_pairsum(p01);
    a10 = d_pairsum(p10); a11 = d_pairsum(p11);
}

// PV for one staged block: accumulate dim-pairs {2l,2l+1},{2l+64,2l+65} x 2 heads.
__device__ __forceinline__ void pv2(const AttnSmem& sm, int l,
                                    float lsA0, float lsB0, float lsA1, float lsB1,
                                    ull& o00, ull& o01, ull& o10, ull& o11) {
#pragma unroll 8
    for (int j = 0; j < BLK_; j++) {
        float pj0 = __shfl_sync(0xffffffffu, (j < 32) ? lsA0 : lsB0, j & 31);
        float pj1 = __shfl_sync(0xffffffffu, (j < 32) ? lsA1 : lsB1, j & 31);
        ull v01 = *(const ull*)&sm.u.kv[j][2 * l];
        ull v23 = *(const ull*)&sm.u.kv[j][2 * l + 64];
        ull d0 = d_dup(pj0), d1 = d_dup(pj1);
        d_fma2(o00, d0, v01); d_fma2(o01, d0, v23);
        d_fma2(o10, d1, v01); d_fma2(o11, d1, v23);
    }
}

__device__ __forceinline__ void softmax8(float (&ls)[8]) {
    float m = -1e30f;
#pragma unroll
    for (int r = 0; r < 8; r++) m = fmaxf(m, ls[r]);
    m = warp_max(m);
    float sum = 0.f;
#pragma unroll
    for (int r = 0; r < 8; r++) {
        ls[r] = (ls[r] > -1e29f) ? expf(ls[r] - m) : 0.f;
        sum += ls[r];
    }
    sum = warp_sum(sum);
    float inv = 1.f / sum;
#pragma unroll
    for (int r = 0; r < 8; r++) ls[r] *= inv;
}

__global__ __launch_bounds__(256) void attn_fused_kernel() {
    const int s = blockIdx.x, g = blockIdx.y;
    __shared__ AttnSmem sm;
    const int tid = threadIdx.x;
    const int w = tid >> 5, l = tid & 31;
    const int h0 = 2 * w, h1 = 2 * w + 1;

    // stage q [16][128] (512 float4 / 256 thr)
    for (int i = tid; i < HG_ * 32; i += 256) {
        int hh = i >> 5, d4 = i & 31;
        *(float4*)&sm.qsh[hh][d4 * 4] =
            *(const float4*)&g_q[(s * H_ + g * HG_ + hh) * DQ_ + d4 * 4];
    }
    // stage kc/vc [2][16][128] (1024 float4)
    for (int i = tid; i < 2 * C_ * 32; i += 256) {
        int part = i >> 9, c = (i >> 5) & 15, d4 = i & 31;
        const float* src = part ? g_vc : g_kc;
        *(float4*)&sm.u.cmp[part][c][d4 * 4] =
            *(const float4*)&src[(c * G_ + g) * DQ_ + d4 * 4];
    }
    __syncthreads();

    // ---------------- cmp logits: lane = (head-half, block) ----------------
    const int hloc = l >> 4;        // 0 or 1
    const int cb = l & 15;          // block id
    const int myh = 2 * w + hloc;
    {
        ull acc0 = 0, acc1 = 0;
#pragma unroll
        for (int d4 = 0; d4 < 32; d4++) {
            ulonglong2 kp = *(const ulonglong2*)&sm.u.cmp[0][cb][d4 * 4];
            ulonglong2 qp = *(const ulonglong2*)&sm.qsh[myh][d4 * 4];
            d_fma2(acc0, qp.x, kp.x);
            d_fma2(acc1, qp.y, kp.y);
        }
        float lg = (d_pairsum(acc0) + d_pairsum(acc1)) * SCALE_;
        const int ncmp = (s + 1) >> 6;
        lg = (cb < ncmp) ? lg : -1e30f;
        // softmax over the 16 lanes of this head-half
        float m = lg;
#pragma unroll
        for (int o = 8; o > 0; o >>= 1) m = fmaxf(m, __shfl_xor_sync(0xffffffffu, m, o));
        float e = (lg > -1e29f) ? expf(lg - m) : 0.f;
        float ssum = e;
#pragma unroll
        for (int o = 8; o > 0; o >>= 1) ssum += __shfl_xor_sync(0xffffffffu, ssum, o);
        float pc = (ssum > 0.f) ? e / ssum : 0.f;
        sm.pw[myh][cb] = pc;
    }
    __syncthreads();

    // top-4 (stable, matches jax.lax.top_k) — thread 0
    if (tid == 0) {
        const int cur = s >> 6;
        float imp[C_];
        for (int c = 0; c < C_; c++) {
            float v;
            if (c > cur) v = -1e9f;
            else if (c == 0 || c == cur) v = 1e9f;
            else {
                v = 0.f;
                for (int hh = 0; hh < HG_; hh++) v += sm.pw[hh][c];
            }
            imp[c] = v;
        }
        bool tk[C_];
        for (int c = 0; c < C_; c++) tk[c] = false;
        for (int t = 0; t < TOPN_; t++) {
            float best = -3e38f;
            int bi = 0;
            for (int c = 0; c < C_; c++)
                if (!tk[c] && imp[c] > best) { best = imp[c]; bi = c; }
            tk[bi] = true;
            sm.idxs[t] = bi;
        }
    }

    // o_cmp into registers (reads vcs; must finish before kv restage)
    ull oC[2][2] = {{0, 0}, {0, 0}};
#pragma unroll
    for (int c = 0; c < C_; c++) {
        float p0 = sm.pw[h0][c], p1 = sm.pw[h1][c];
        ull v01 = *(const ull*)&sm.u.cmp[1][c][2 * l];
        ull v23 = *(const ull*)&sm.u.cmp[1][c][2 * l + 64];
        ull d0 = d_dup(p0), d1 = d_dup(p1);
        d_fma2(oC[0][0], d0, v01); d_fma2(oC[0][1], d0, v23);
        d_fma2(oC[1][0], d1, v01); d_fma2(oC[1][1], d1, v23);
    }
    __syncthreads();

    int blk[TOPN_];
#pragma unroll
    for (int n = 0; n < TOPN_; n++) blk[n] = sm.idxs[n];

    // ---------------- selected branch ----------------
    float ls0[8], ls1[8];
#pragma unroll
    for (int n = 0; n < TOPN_; n++) {
        const int t0 = blk[n] * BLK_;
        stage_kv256(sm, g_k, t0, g, tid);
        __syncthreads();
        float a00, a01, a10, a11;
        qk2(sm, h0, h1, l, a00, a01, a10, a11);
        bool ok0 = (t0 + l <= s), ok1 = (t0 + l + 32 <= s);
        ls0[n * 2 + 0] = ok0 ? a00 * SCALE_ : -1e30f;
        ls0[n * 2 + 1] = ok1 ? a01 * SCALE_ : -1e30f;
        ls1[n * 2 + 0] = ok0 ? a10 * SCALE_ : -1e30f;
        ls1[n * 2 + 1] = ok1 ? a11 * SCALE_ : -1e30f;
        __syncthreads();
    }
    softmax8(ls0);
    softmax8(ls1);
    ull oS[2][2] = {{0, 0}, {0, 0}};
#pragma unroll
    for (int n = 0; n < TOPN_; n++) {
        stage_kv256(sm, g_v, blk[n] * BLK_, g, tid);
        __syncthreads();
        pv2(sm, l, ls0[n * 2], ls0[n * 2 + 1], ls1[n * 2], ls1[n * 2 + 1],
            oS[0][0], oS[0][1], oS[1][0], oS[1][1]);
        __syncthreads();
    }

    // ---------------- window branch ----------------
    const int wstart = (s >= WIN_) ? (s - WIN_ + 1) : 0;
#pragma unroll
    for (int n = 0; n < 4; n++) {
        const int t0 = wstart + n * BLK_;
        stage_kv256(sm, g_k, t0, g, tid);
        __syncthreads();
        float a00, a01, a10, a11;
        qk2(sm, h0, h1, l, a00, a01, a10, a11);
        bool ok0 = (t0 + l <= s), ok1 = (t0 + l + 32 <= s);
        ls0[n * 2 + 0] = ok0 ? a00 * SCALE_ : -1e30f;
        ls0[n * 2 + 1] = ok1 ? a01 * SCALE_ : -1e30f;
        ls1[n * 2 + 0] = ok0 ? a10 * SCALE_ : -1e30f;
        ls1[n * 2 + 1] = ok1 ? a11 * SCALE_ : -1e30f;
        __syncthreads();
    }
    softmax8(ls0);
    softmax8(ls1);
    ull oW[2][2] = {{0, 0}, {0, 0}};
#pragma unroll
    for (int n = 0; n < 4; n++) {
        stage_kv256(sm, g_v, wstart + n * BLK_, g, tid);
        __syncthreads();
        pv2(sm, l, ls0[n * 2], ls0[n * 2 + 1], ls1[n * 2], ls1[n * 2 + 1],
            oW[0][0], oW[0][1], oW[1][0], oW[1][1]);
        __syncthreads();
    }

    // ---------------- gated combine, single write ----------------
#pragma unroll
    for (int hi = 0; hi < 2; hi++) {
        const int h = g * HG_ + 2 * w + hi;
        const float* gp = &g_gates[(s * H_ + h) * 3];
        float g0 = gp[0], g1 = gp[1], g2 = gp[2];
        float2 c0 = d_unpack(oC[hi][0]), c1 = d_unpack(oC[hi][1]);
        float2 s0 = d_unpack(oS[hi][0]), s1 = d_unpack(oS[hi][1]);
        float2 w0 = d_unpack(oW[hi][0]), w1 = d_unpack(oW[hi][1]);
        float* op = &g_ocomb[(s * H_ + h) * DV_];
        *(float2*)&op[2 * l] =
            make_float2(g0 * c0.x + g1 * s0.x + g2 * w0.x,
                        g0 * c0.y + g1 * s0.y + g2 * w0.y);
        *(float2*)&op[2 * l + 64] =
            make_float2(g0 * c1.x + g1 * s1.x + g2 * w1.x,
                        g0 * c1.y + g1 * s1.y + g2 * w1.y);
    }
}

// ---------------------------------------------------------------------------
extern "C" void kernel_launch(void* const* d_in, const int* in_sizes, int n_in,
                              void* d_out, int out_size) {
    const float* x    = (const float*)d_in[0];
    const float* cosp = (const float*)d_in[1];
    const float* sinp = (const float*)d_in[2];
    const float* Wq   = (const float*)d_in[3];
    const float* Wk   = (const float*)d_in[4];
    const float* Wv   = (const float*)d_in[5];
    const float* Wo   = (const float*)d_in[6];
    const float* Wc   = (const float*)d_in[7];
    float* out = (float*)d_out;

    float *p_qraw, *p_kraw, *p_v, *p_gates;
    cudaGetSymbolAddress((void**)&p_qraw, g_qraw);
    cudaGetSymbolAddress((void**)&p_kraw, g_kraw);
    cudaGetSymbolAddress((void**)&p_v, g_v);
    cudaGetSymbolAddress((void**)&p_gates, g_gates);

    cudaFuncSetAttribute(fused_proj_mma,
                         cudaFuncAttributeMaxDynamicSharedMemorySize, GEMM_SMEM);
    cudaFuncSetAttribute(gemm_out_mma,
                         cudaFuncAttributeMaxDynamicSharedMemorySize, GEMM_SMEM);

    // 1: split conversions
    cvt_all_kernel<<<(5029888 + 255) / 256, 256>>>(x, Wq, Wk, Wv, Wc, Wo);

    // 2: fused projections (tensor cores)
    fused_proj_mma<<<dim3(37, 8), 256, GEMM_SMEM>>>(p_qraw, p_kraw, p_v, p_gates);

    // 3: rope q/k + sigmoid + block means (kc/vc from raw)
    const int ew_total = S_ * NQ_ + S_ * NKV_ + S_ * NC_ + C_ * G_ * DQ_;
    ew_all_kernel<<<(ew_total + 255) / 256, 256>>>(cosp, sinp);

    // 4: fused attention (cmp + top-4 + slc + win) — ncu capture slot
    attn_fused_kernel<<<dim3(S_, G_), 256>>>();

    // 5: split ocomb; 6: output projection
    cvt_ocomb_kernel<<<(S_ * H_ * DV_ / 4 + 255) / 256, 256>>>();
    gemm_out_mma<<<dim3(16, 8), 256, GEMM_SMEM>>>(out);
}

// round 17
// speedup vs baseline: 1.9322x; 1.3141x over previous
#include <cuda_runtime.h>
#include <cuda_bf16.h>

// ---------------------------------------------------------------------------
// NSA forward. R10: attention QK/PV moved to mma.sync tensor cores with
// 3-term split-bf16 (same scheme as the GEMMs). ew_all emits roped q/k and v
// as bf16 hi/lo planes. cmp branch scalar. GEMMs unchanged (R8 proven).
// ---------------------------------------------------------------------------

namespace {
constexpr int S_ = 1024;
constexpr int D_ = 2048;
constexpr int H_ = 32;
constexpr int G_ = 2;
constexpr int HG_ = 16;
constexpr int DQ_ = 128;
constexpr int DV_ = 128;
constexpr int BLK_ = 64;
constexpr int C_ = 16;
constexpr int TOPN_ = 4;
constexpr int WIN_ = 256;
constexpr int NQ_ = H_ * DQ_;   // 4096
constexpr int NKV_ = G_ * DQ_;  // 256
constexpr int NC_ = H_ * 3;     // 96
constexpr float SCALE_ = 0.08838834764831845f;

constexpr unsigned OFF_AL = 8192;
constexpr unsigned OFF_BH = 16384;
constexpr unsigned OFF_BL = 25088;
constexpr unsigned STAGE_BYTES = 33792;
constexpr unsigned GEMM_SMEM = 2 * STAGE_BYTES;  // 67584
}

typedef unsigned long long ull;

// fp32 scratch
__device__ float g_qraw[S_ * NQ_];
__device__ float g_kraw[S_ * NKV_];
__device__ float g_v[S_ * NKV_];
__device__ float g_gates[S_ * NC_];
__device__ float g_kc[C_ * G_ * DQ_];
__device__ float g_vc[C_ * G_ * DV_];
__device__ float g_ocomb[S_ * H_ * DV_];

// bf16 split planes (GEMM inputs)
__device__ __align__(16) __nv_bfloat16 g_xh[S_ * D_],  g_xl[S_ * D_];
__device__ __align__(16) __nv_bfloat16 g_Wqh[D_ * NQ_], g_Wql[D_ * NQ_];
__device__ __align__(16) __nv_bfloat16 g_Wkh[D_ * NKV_], g_Wkl[D_ * NKV_];
__device__ __align__(16) __nv_bfloat16 g_Wvh[D_ * NKV_], g_Wvl[D_ * NKV_];
__device__ __align__(16) __nv_bfloat16 g_Wch[D_ * NC_],  g_Wcl[D_ * NC_];
__device__ __align__(16) __nv_bfloat16 g_Woh[H_ * DV_ * D_], g_Wol[H_ * DV_ * D_];
__device__ __align__(16) __nv_bfloat16 g_oh[S_ * H_ * DV_], g_ol[S_ * H_ * DV_];

// bf16 split planes (attention inputs: roped q/k, v)
__device__ __align__(16) __nv_bfloat16 g_aqh[S_ * NQ_], g_aql[S_ * NQ_];
__device__ __align__(16) __nv_bfloat16 g_akh[S_ * NKV_], g_akl[S_ * NKV_];
__device__ __align__(16) __nv_bfloat16 g_avh[S_ * NKV_], g_avl[S_ * NKV_];

__device__ __forceinline__ float warp_sum(float v) {
#pragma unroll
    for (int o = 16; o > 0; o >>= 1) v += __shfl_xor_sync(0xffffffffu, v, o);
    return v;
}
__device__ __forceinline__ float warp_max(float v) {
#pragma unroll
    for (int o = 16; o > 0; o >>= 1) v = fmaxf(v, __shfl_xor_sync(0xffffffffu, v, o));
    return v;
}

// ---- f32x2 helpers ---------------------------------------------------------
__device__ __forceinline__ ull d_dup(float v) {
    ull r;
    asm("mov.b64 %0, {%1, %1};" : "=l"(r) : "f"(v));
    return r;
}
__device__ __forceinline__ float2 d_unpack(ull p) {
    float lo, hi;
    asm("mov.b64 {%0, %1}, %2;" : "=f"(lo), "=f"(hi) : "l"(p));
    return make_float2(lo, hi);
}
__device__ __forceinline__ void d_fma2(ull& d, ull a, ull b) {
    asm("fma.rn.f32x2 %0, %1, %2, %0;" : "+l"(d) : "l"(a), "l"(b));
}
__device__ __forceinline__ float d_pairsum(ull p) {
    float2 u = d_unpack(p);
    return u.x + u.y;
}

// ---- tensor-core / async primitives ---------------------------------------
__device__ __forceinline__ void ldsm_x4(unsigned (&r)[4], unsigned saddr) {
    asm volatile("ldmatrix.sync.aligned.m8n8.x4.shared.b16 {%0,%1,%2,%3}, [%4];"
                 : "=r"(r[0]), "=r"(r[1]), "=r"(r[2]), "=r"(r[3]) : "r"(saddr));
}
__device__ __forceinline__ void ldsm_x4_t(unsigned (&r)[4], unsigned saddr) {
    asm volatile("ldmatrix.sync.aligned.m8n8.x4.trans.shared.b16 {%0,%1,%2,%3}, [%4];"
                 : "=r"(r[0]), "=r"(r[1]), "=r"(r[2]), "=r"(r[3]) : "r"(saddr));
}
__device__ __forceinline__ void mma_bf16(float (&c)[4], const unsigned (&a)[4],
                                         unsigned b0, unsigned b1) {
    asm("mma.sync.aligned.m16n8k16.row.col.f32.bf16.bf16.f32 "
        "{%0,%1,%2,%3}, {%4,%5,%6,%7}, {%8,%9}, {%0,%1,%2,%3};"
        : "+f"(c[0]), "+f"(c[1]), "+f"(c[2]), "+f"(c[3])
        : "r"(a[0]), "r"(a[1]), "r"(a[2]), "r"(a[3]), "r"(b0), "r"(b1));
}
__device__ __forceinline__ void cp16(unsigned dst, const void* src, bool valid) {
    int sz = valid ? 16 : 0;
    asm volatile("cp.async.cg.shared.global [%0], [%1], 16, %2;"
                 :: "r"(dst), "l"(src), "r"(sz));
}
#define CP_COMMIT() asm volatile("cp.async.commit_group;")
#define CP_WAIT(n) asm volatile("cp.async.wait_group %0;" :: "n"(n))

__device__ __forceinline__ unsigned swA(int r, int c) {
    return (unsigned)(r * 64) + ((unsigned)(c ^ ((r >> 1) & 3)) << 4);
}

// ---------------------------------------------------------------------------
// Fused split-convert (GEMM inputs)
// ---------------------------------------------------------------------------
__global__ __launch_bounds__(256) void cvt_all_kernel(
    const float* __restrict__ x, const float* __restrict__ Wq,
    const float* __restrict__ Wk, const float* __restrict__ Wv,
    const float* __restrict__ Wc, const float* __restrict__ Wo) {
    long long i = (long long)blockIdx.x * 256 + threadIdx.x;
    const float* src;
    __nv_bfloat16 *hi, *lo;
    long long off;
    if (i < 524288)       { src = x;  hi = g_xh;  lo = g_xl;  off = i; }
    else if (i < 2621440) { src = Wq; hi = g_Wqh; lo = g_Wql; off = i - 524288; }
    else if (i < 2752512) { src = Wk; hi = g_Wkh; lo = g_Wkl; off = i - 2621440; }
    else if (i < 2883584) { src = Wv; hi = g_Wvh; lo = g_Wvl; off = i - 2752512; }
    else if (i < 2932736) { src = Wc; hi = g_Wch; lo = g_Wcl; off = i - 2883584; }
    else if (i < 5029888) { src = Wo; hi = g_Woh; lo = g_Wol; off = i - 2932736; }
    else return;
    float4 v = ((const float4*)src)[off];
    __nv_bfloat16 h0 = __float2bfloat16(v.x), h1 = __float2bfloat16(v.y);
    __nv_bfloat16 h2 = __float2bfloat16(v.z), h3 = __float2bfloat16(v.w);
    __nv_bfloat162 a, b;
    a.x = h0; a.y = h1; b.x = h2; b.y = h3;
    ((__nv_bfloat162*)hi)[off * 2] = a;
    ((__nv_bfloat162*)hi)[off * 2 + 1] = b;
    a.x = __float2bfloat16(v.x - __bfloat162float(h0));
    a.y = __float2bfloat16(v.y - __bfloat162float(h1));
    b.x = __float2bfloat16(v.z - __bfloat162float(h2));
    b.y = __float2bfloat16(v.w - __bfloat162float(h3));
    ((__nv_bfloat162*)lo)[off * 2] = a;
    ((__nv_bfloat162*)lo)[off * 2 + 1] = b;
}

__global__ __launch_bounds__(256) void cvt_ocomb_kernel() {
    int i = blockIdx.x * 256 + threadIdx.x;
    if (i >= S_ * H_ * DV_ / 4) return;
    float4 v = ((const float4*)g_ocomb)[i];
    __nv_bfloat16 h0 = __float2bfloat16(v.x), h1 = __float2bfloat16(v.y);
    __nv_bfloat16 h2 = __float2bfloat16(v.z), h3 = __float2bfloat16(v.w);
    __nv_bfloat162 a, b;
    a.x = h0; a.y = h1; b.x = h2; b.y = h3;
    ((__nv_bfloat162*)g_oh)[i * 2] = a;
    ((__nv_bfloat162*)g_oh)[i * 2 + 1] = b;
    a.x = __float2bfloat16(v.x - __bfloat162float(h0));
    a.y = __float2bfloat16(v.y - __bfloat162float(h1));
    b.x = __float2bfloat16(v.z - __bfloat162float(h2));
    b.y = __float2bfloat16(v.w - __bfloat162float(h3));
    ((__nv_bfloat162*)g_ol)[i * 2] = a;
    ((__nv_bfloat162*)g_ol)[i * 2 + 1] = b;
}

// ---------------------------------------------------------------------------
// cp.async double-buffered MMA GEMM (R8 proven, 65.8% tensor pipe).
// ---------------------------------------------------------------------------
__device__ __forceinline__ void gemm_tile_async(
    const __nv_bfloat16* __restrict__ Agh, const __nv_bfloat16* __restrict__ Agl,
    int lda,
    const __nv_bfloat16* __restrict__ Bgh, const __nv_bfloat16* __restrict__ Bgl,
    int ldb,
    float* __restrict__ Cp, int ldc,
    int K, int Nloc, int bm, int bn, char* dynsm) {
    const int tid = threadIdx.x;
    const int lane = tid & 31;
    const int w = tid >> 5;
    const int wm = (w >> 1) * 32;
    const int wn = (w & 1) * 64;

    const int ar0 = tid >> 2, ac0 = tid & 3;
    const int ar1 = ar0 + 64;
    const int br0 = tid >> 4, bc0 = tid & 15;
    const int br1 = br0 + 16;
    const bool bok = (bn + bc0 * 8 + 7) < Nloc;

    const unsigned sbase = (unsigned)__cvta_generic_to_shared(dynsm);

    float c[2][8][4];
#pragma unroll
    for (int i = 0; i < 2; i++)
#pragma unroll
        for (int j = 0; j < 8; j++)
#pragma unroll
            for (int q = 0; q < 4; q++) c[i][j][q] = 0.f;

    auto issue = [&](int step, int stage) {
        const unsigned base = sbase + stage * STAGE_BYTES;
        const int k0 = step * 32;
        cp16(base + swA(ar0, ac0), Agh + (size_t)(bm + ar0) * lda + k0 + ac0 * 8, true);
        cp16(base + swA(ar1, ac0), Agh + (size_t)(bm + ar1) * lda + k0 + ac0 * 8, true);
        cp16(base + OFF_AL + swA(ar0, ac0), Agl + (size_t)(bm + ar0) * lda + k0 + ac0 * 8, true);
        cp16(base + OFF_AL + swA(ar1, ac0), Agl + (size_t)(bm + ar1) * lda + k0 + ac0 * 8, true);
        const __nv_bfloat16* b0 = bok ? Bgh + (size_t)(k0 + br0) * ldb + bn + bc0 * 8 : Bgh;
        const __nv_bfloat16* b1 = bok ? Bgh + (size_t)(k0 + br1) * ldb + bn + bc0 * 8 : Bgh;
        const __nv_bfloat16* b2 = bok ? Bgl + (size_t)(k0 + br0) * ldb + bn + bc0 * 8 : Bgl;
        const __nv_bfloat16* b3 = bok ? Bgl + (size_t)(k0 + br1) * ldb + bn + bc0 * 8 : Bgl;
        cp16(base + OFF_BH + br0 * 272 + bc0 * 16, b0, bok);
        cp16(base + OFF_BH + br1 * 272 + bc0 * 16, b1, bok);
        cp16(base + OFF_BL + br0 * 272 + bc0 * 16, b2, bok);
        cp16(base + OFF_BL + br1 * 272 + bc0 * 16, b3, bok);
    };

    const int nSteps = K >> 5;
    issue(0, 0);
    CP_COMMIT();

    for (int step = 0; step < nSteps; step++) {
        const int cur = step & 1;
        if (step + 1 < nSteps) {
            issue(step + 1, cur ^ 1);
            CP_COMMIT();
            CP_WAIT(1);
        } else {
            CP_WAIT(0);
        }
        __syncthreads();

        const unsigned base = sbase + cur * STAGE_BYTES;
#pragma unroll
        for (int kk = 0; kk < 2; kk++) {
            unsigned ah[2][4], al[2][4], bh[4][4], bl[4][4];
#pragma unroll
            for (int i = 0; i < 2; i++) {
                int arow = wm + 16 * i + (lane & 15);
                int achunk = kk * 2 + (lane >> 4);
                unsigned off = swA(arow, achunk);
                ldsm_x4(ah[i], base + off);
                ldsm_x4(al[i], base + OFF_AL + off);
            }
#pragma unroll
            for (int j = 0; j < 4; j++) {
                unsigned brow = kk * 16 + (lane & 15);
                unsigned bcol = wn + 16 * j + 8 * (lane >> 4);
                unsigned off = brow * 272 + bcol * 2;
                ldsm_x4_t(bh[j], base + OFF_BH + off);
                ldsm_x4_t(bl[j], base + OFF_BL + off);
            }
#pragma unroll
            for (int i = 0; i < 2; i++)
#pragma unroll
                for (int jn = 0; jn < 8; jn++)
                    mma_bf16(c[i][jn], ah[i], bh[jn >> 1][(jn & 1) * 2],
                             bh[jn >> 1][(jn & 1) * 2 + 1]);
#pragma unroll
            for (int i = 0; i < 2; i++)
#pragma unroll
                for (int jn = 0; jn < 8; jn++)
                    mma_bf16(c[i][jn], ah[i], bl[jn >> 1][(jn & 1) * 2],
                             bl[jn >> 1][(jn & 1) * 2 + 1]);
#pragma unroll
            for (int i = 0; i < 2; i++)
#pragma unroll
                for (int jn = 0; jn < 8; jn++)
                    mma_bf16(c[i][jn], al[i], bh[jn >> 1][(jn & 1) * 2],
                             bh[jn >> 1][(jn & 1) * 2 + 1]);
        }
        __syncthreads();
    }

    const int qrow = lane >> 2;
    const int qcol = (lane & 3) * 2;
#pragma unroll
    for (int i = 0; i < 2; i++) {
        const int row0 = bm + wm + 16 * i + qrow;
#pragma unroll
        for (int jn = 0; jn < 8; jn++) {
            const int col = bn + wn + jn * 8 + qcol;
            if (col < Nloc) {
                *(float2*)&Cp[(size_t)row0 * ldc + col] =
                    make_float2(c[i][jn][0], c[i][jn][1]);
                *(float2*)&Cp[(size_t)(row0 + 8) * ldc + col] =
                    make_float2(c[i][jn][2], c[i][jn][3]);
            }
        }
    }
}

__global__ __launch_bounds__(256) void fused_proj_mma(
    float* __restrict__ qraw, float* __restrict__ kraw,
    float* __restrict__ v, float* __restrict__ gates) {
    extern __shared__ char dynsm[];
    const int t = blockIdx.x;
    const int bm = blockIdx.y * 128;
    const __nv_bfloat16 *Bh, *Bl;
    float* Cp;
    int Nloc, bn;
    if (t < 32)      { Bh = g_Wqh; Bl = g_Wql; Cp = qraw;  Nloc = NQ_;  bn = t * 128; }
    else if (t < 34) { Bh = g_Wkh; Bl = g_Wkl; Cp = kraw;  Nloc = NKV_; bn = (t - 32) * 128; }
    else if (t < 36) { Bh = g_Wvh; Bl = g_Wvl; Cp = v;     Nloc = NKV_; bn = (t - 34) * 128; }
    else             { Bh = g_Wch; Bl = g_Wcl; Cp = gates; Nloc = NC_;  bn = 0; }
    gemm_tile_async(g_xh, g_xl, D_, Bh, Bl, Nloc, Cp, Nloc, D_, Nloc, bm, bn, dynsm);
}

__global__ __launch_bounds__(256) void gemm_out_mma(float* __restrict__ out) {
    extern __shared__ char dynsm[];
    gemm_tile_async(g_oh, g_ol, H_ * DV_, g_Woh, g_Wol, D_, out, D_,
                    H_ * DV_, D_, blockIdx.y * 128, blockIdx.x * 128, dynsm);
}

// ---------------------------------------------------------------------------
// Fused elementwise: rope q -> aq planes, rope k -> ak planes, sigmoid,
// kc/vc means, v -> av planes.
// ---------------------------------------------------------------------------
__device__ __forceinline__ void split_store(__nv_bfloat16* hp, __nv_bfloat16* lp,
                                            long long i, float v) {
    __nv_bfloat16 h = __float2bfloat16(v);
    hp[i] = h;
    lp[i] = __float2bfloat16(v - __bfloat162float(h));
}

__global__ __launch_bounds__(256) void ew_all_kernel(const float* __restrict__ cosp,
                                                     const float* __restrict__ sinp) {
    int i = blockIdx.x * 256 + threadIdx.x;
    if (i < S_ * NQ_) {  // rope q -> split planes
        int d = i & 127;
        int s = i >> 12;
        float c = cosp[s * DQ_ + d], sn = sinp[s * DQ_ + d];
        float t = g_qraw[i];
        float rot = (d < 64) ? -g_qraw[i + 64] : g_qraw[i - 64];
        split_store(g_aqh, g_aql, i, t * c + rot * sn);
        return;
    }
    i -= S_ * NQ_;
    if (i < S_ * NKV_) {  // rope k -> split planes
        int d = i & 127;
        int s = i >> 8;
        float c = cosp[s * DQ_ + d], sn = sinp[s * DQ_ + d];
        float t = g_kraw[i];
        float rot = (d < 64) ? -g_kraw[i + 64] : g_kraw[i - 64];
        split_store(g_akh, g_akl, i, t * c + rot * sn);
        return;
    }
    i -= S_ * NKV_;
    if (i < S_ * NKV_) {  // v -> split planes
        split_store(g_avh, g_avl, i, g_v[i]);
        return;
    }
    i -= S_ * NKV_;
    if (i < S_ * NC_) {
        g_gates[i] = 1.f / (1.f + expf(-g_gates[i]));
        return;
    }
    i -= S_ * NC_;
    if (i < C_ * G_ * DQ_) {
        int d = i & 127;
        int g = (i >> 7) & 1;
        int c = i >> 8;
        float sk = 0.f, sv = 0.f;
        for (int j = 0; j < BLK_; j++) {
            int t = c * BLK_ + j;
            float kr = g_kraw[(t * G_ + g) * DQ_ + d];
            float rot = (d < 64) ? -g_kraw[(t * G_ + g) * DQ_ + d + 64]
                                 : g_kraw[(t * G_ + g) * DQ_ + d - 64];
            sk += kr * cosp[t * DQ_ + d] + rot * sinp[t * DQ_ + d];
            sv += g_v[(t * G_ + g) * DV_ + d];
        }
        g_kc[i] = sk * (1.f / 64.f);
        g_vc[i] = sv * (1.f / 64.f);
    }
}

// ---------------------------------------------------------------------------
// Fused attention with tensor-core QK/PV.
// One CTA per (s, g), 256 threads = 8 warps.
// ---------------------------------------------------------------------------
namespace {
constexpr int KP_ = 136;   // bf16 row stride for K/V/Q tiles
constexpr int LP_ = 268;   // float row stride for logits
constexpr int PP_ = 264;   // bf16 row stride for P planes
}

struct AttnSmem {
    union {
        struct { __nv_bfloat16 kh[BLK_][KP_]; __nv_bfloat16 kl[BLK_][KP_]; } t;
        float cmp[2][C_][DQ_];
    } u;                                   // 34816
    __nv_bfloat16 qh[HG_][KP_];            // 4352
    __nv_bfloat16 ql[HG_][KP_];            // 4352
    float L[HG_][LP_];                     // 17152
    __nv_bfloat16 Ph[HG_][PP_];            // 8448
    __nv_bfloat16 Pl[HG_][PP_];            // 8448
    float Ocmp[HG_][DQ_];                  // 8192
    float pw[HG_][C_];                     // 1024
    int idxs[TOPN_];
};

__device__ __forceinline__ void stage_kv_bf(AttnSmem& sm,
                                            const __nv_bfloat16* __restrict__ srch,
                                            const __nv_bfloat16* __restrict__ srcl,
                                            int t0, int g, int tid) {
    for (int i = tid; i < 2048; i += 256) {
        int plane = i >> 10, j = (i >> 4) & 63, c16 = i & 15;
        const __nv_bfloat16* src = plane ? srcl : srch;
        uint4 vv = *(const uint4*)&src[((size_t)(t0 + j) * G_ + g) * DQ_ + c16 * 8];
        __nv_bfloat16* dst = plane ? &sm.u.t.kl[0][0] : &sm.u.t.kh[0][0];
        *(uint4*)&dst[j * KP_ + c16 * 8] = vv;
    }
}

// One branch (4 blocks): logits -> softmax -> P planes -> PV accumulate.
__device__ __forceinline__ void attn_branch(AttnSmem& sm, const int (&bs)[4],
                                            int s, int g, int tid, int w, int lane,
                                            unsigned sQh, unsigned sQl,
                                            unsigned sKh, unsigned sKl,
                                            unsigned sPh, unsigned sPl,
                                            float (&cV)[2][4]) {
    const int n0 = w * 8;
    // ---- logits ----
#pragma unroll
    for (int bb = 0; bb < 4; bb++) {
        stage_kv_bf(sm, g_akh, g_akl, bs[bb], g, tid);
        __syncthreads();
        float cQ[4] = {0.f, 0.f, 0.f, 0.f};
#pragma unroll
        for (int kk = 0; kk < 4; kk++) {
            const int ka = kk * 32;
            unsigned aH0[4], aH1[4], aL0[4], aL1[4], bH[4], bL[4];
            unsigned aoff0 = (unsigned)(((lane & 15) * KP_ + ka + 8 * (lane >> 4)) * 2);
            unsigned aoff1 = aoff0 + 32;
            ldsm_x4(aH0, sQh + aoff0);
            ldsm_x4(aH1, sQh + aoff1);
            ldsm_x4(aL0, sQl + aoff0);
            ldsm_x4(aL1, sQl + aoff1);
            unsigned boff = (unsigned)(((n0 + (lane & 7)) * KP_ + ka + 8 * (lane >> 3)) * 2);
            ldsm_x4(bH, sKh + boff);
            ldsm_x4(bL, sKl + boff);
            mma_bf16(cQ, aH0, bH[0], bH[1]);
            mma_bf16(cQ, aH0, bL[0], bL[1]);
            mma_bf16(cQ, aL0, bH[0], bH[1]);
            mma_bf16(cQ, aH1, bH[2], bH[3]);
            mma_bf16(cQ, aH1, bL[2], bL[3]);
            mma_bf16(cQ, aL1, bH[2], bH[3]);
        }
        const int qrow = lane >> 2, qcol = lane & 3;
        const int colb = bb * 64 + n0 + 2 * qcol;
        sm.L[qrow][colb] = cQ[0];
        sm.L[qrow][colb + 1] = cQ[1];
        sm.L[qrow + 8][colb] = cQ[2];
        sm.L[qrow + 8][colb + 1] = cQ[3];
        __syncthreads();
    }
    // ---- softmax + P planes (warp w: heads 2w, 2w+1) ----
#pragma unroll
    for (int hi = 0; hi < 2; hi++) {
        const int hh = 2 * w + hi;
        float lv[8];
#pragma unroll
        for (int ch = 0; ch < 8; ch++) {
            int col = ch * 32 + lane;
            int bb = ch >> 1, j = col & 63;
            lv[ch] = (bs[bb] + j <= s) ? sm.L[hh][col] * SCALE_ : -1e30f;
        }
        float m = -1e30f;
#pragma unroll
        for (int ch = 0; ch < 8; ch++) m = fmaxf(m, lv[ch]);
        m = warp_max(m);
        float sum = 0.f;
#pragma unroll
        for (int ch = 0; ch < 8; ch++) {
            lv[ch] = (lv[ch] > -1e29f) ? expf(lv[ch] - m) : 0.f;
            sum += lv[ch];
        }
        sum = warp_sum(sum);
        float inv = 1.f / sum;
#pragma unroll
        for (int ch = 0; ch < 8; ch++) {
            float p = lv[ch] * inv;
            int col = ch * 32 + lane;
            __nv_bfloat16 ph = __float2bfloat16(p);
            sm.Ph[hh][col] = ph;
            sm.Pl[hh][col] = __float2bfloat16(p - __bfloat162float(ph));
        }
    }
    __syncthreads();
    // ---- PV ----
    const int n0v = w * 16;
#pragma unroll
    for (int bb = 0; bb < 4; bb++) {
        stage_kv_bf(sm, g_avh, g_avl, bs[bb], g, tid);
        __syncthreads();
#pragma unroll
        for (int kk = 0; kk < 4; kk++) {
            unsigned aH[4], aL[4], bH[4], bL[4];
            unsigned aoff = (unsigned)(((lane & 15) * PP_ + bb * 64 + kk * 16 +
                                        8 * (lane >> 4)) * 2);
            ldsm_x4(aH, sPh + aoff);
            ldsm_x4(aL, sPl + aoff);
            unsigned boff = (unsigned)(((kk * 16 + (lane & 15)) * KP_ + n0v +
                                        8 * (lane >> 4)) * 2);
            ldsm_x4_t(bH, sKh + boff);
            ldsm_x4_t(bL, sKl + boff);
            mma_bf16(cV[0], aH, bH[0], bH[1]);
            mma_bf16(cV[0], aH, bL[0], bL[1]);
            mma_bf16(cV[0], aL, bH[0], bH[1]);
            mma_bf16(cV[1], aH, bH[2], bH[3]);
            mma_bf16(cV[1], aH, bL[2], bL[3]);
            mma_bf16(cV[1], aL, bH[2], bH[3]);
        }
        __syncthreads();
    }
}

__global__ __launch_bounds__(256) void attn_fused_kernel() {
    extern __shared__ char smraw[];
    AttnSmem& sm = *reinterpret_cast<AttnSmem*>(smraw);
    const int s = blockIdx.x, g = blockIdx.y;
    const int tid = threadIdx.x;
    const int w = tid >> 5, lane = tid & 31;

    const unsigned sQh = (unsigned)__cvta_generic_to_shared(&sm.qh[0][0]);
    const unsigned sQl = (unsigned)__cvta_generic_to_shared(&sm.ql[0][0]);
    const unsigned sKh = (unsigned)__cvta_generic_to_shared(&sm.u.t.kh[0][0]);
    const unsigned sKl = (unsigned)__cvta_generic_to_shared(&sm.u.t.kl[0][0]);
    const unsigned sPh = (unsigned)__cvta_generic_to_shared(&sm.Ph[0][0]);
    const unsigned sPl = (unsigned)__cvta_generic_to_shared(&sm.Pl[0][0]);

    // stage q planes + cmp kc/vc tiles
    for (int i = tid; i < 512; i += 256) {
        int plane = i >> 8, hh = (i >> 4) & 15, c16 = i & 15;
        const __nv_bfloat16* src = plane ? g_aql : g_aqh;
        uint4 vv = *(const uint4*)&src[(size_t)(s * H_ + g * HG_ + hh) * DQ_ + c16 * 8];
        __nv_bfloat16* dst = plane ? &sm.ql[0][0] : &sm.qh[0][0];
        *(uint4*)&dst[hh * KP_ + c16 * 8] = vv;
    }
    for (int i = tid; i < 2 * C_ * 32; i += 256) {
        int part = i >> 9, c = (i >> 5) & 15, d4 = i & 31;
        const float* src = part ? g_vc : g_kc;
        *(float4*)&sm.u.cmp[part][c][d4 * 4] =
            *(const float4*)&src[(c * G_ + g) * DQ_ + d4 * 4];
    }
    __syncthreads();

    // ---- cmp logits: lane = (head-half, block); q = qh+ql reconstructed ----
    const int hloc = lane >> 4, cb = lane & 15;
    const int myh = 2 * w + hloc;
    {
        float acc = 0.f;
#pragma unroll
        for (int c8 = 0; c8 < 16; c8++) {
            uint4 qhv = *(const uint4*)&sm.qh[myh][c8 * 8];
            uint4 qlv = *(const uint4*)&sm.ql[myh][c8 * 8];
            const float* kp = &sm.u.cmp[0][cb][c8 * 8];
            const unsigned* qh4 = &qhv.x;
            const unsigned* ql4 = &qlv.x;
#pragma unroll
            for (int p2 = 0; p2 < 4; p2++) {
                float2 qa = __bfloat1622float2(
                    *reinterpret_cast<const __nv_bfloat162*>(&qh4[p2]));
                float2 qb = __bfloat1622float2(
                    *reinterpret_cast<const __nv_bfloat162*>(&ql4[p2]));
                acc += (qa.x + qb.x) * kp[p2 * 2] + (qa.y + qb.y) * kp[p2 * 2 + 1];
            }
        }
        float lg = acc * SCALE_;
        const int ncmp = (s + 1) >> 6;
        lg = (cb < ncmp) ? lg : -1e30f;
        float m = lg;
#pragma unroll
        for (int o = 8; o > 0; o >>= 1) m = fmaxf(m, __shfl_xor_sync(0xffffffffu, m, o));
        float e = (lg > -1e29f) ? expf(lg - m) : 0.f;
        float ssum = e;
#pragma unroll
        for (int o = 8; o > 0; o >>= 1) ssum += __shfl_xor_sync(0xffffffffu, ssum, o);
        sm.pw[myh][cb] = (ssum > 0.f) ? e / ssum : 0.f;
    }
    __syncthreads();

    // top-4 (stable) — thread 0
    if (tid == 0) {
        const int cur = s >> 6;
        float imp[C_];
        for (int c = 0; c < C_; c++) {
            float v;
            if (c > cur) v = -1e9f;
            else if (c == 0 || c == cur) v = 1e9f;
            else {
                v = 0.f;
                for (int hh = 0; hh < HG_; hh++) v += sm.pw[hh][c];
            }
            imp[c] = v;
        }
        bool tk[C_];
        for (int c = 0; c < C_; c++) tk[c] = false;
        for (int t = 0; t < TOPN_; t++) {
            float best = -3e38f;
            int bi = 0;
            for (int c = 0; c < C_; c++)
                if (!tk[c] && imp[c] > best) { best = imp[c]; bi = c; }
            tk[bi] = true;
            sm.idxs[t] = bi;
        }
    }

    // o_cmp -> smem Ocmp (lane dims 2l..2l+1, 2l+64..2l+65; heads 2w, 2w+1)
    {
        const int h0 = 2 * w, h1 = 2 * w + 1;
        ull oC[2][2] = {{0, 0}, {0, 0}};
#pragma unroll
        for (int c = 0; c < C_; c++) {
            float p0 = sm.pw[h0][c], p1 = sm.pw[h1][c];
            ull v01 = *(const ull*)&sm.u.cmp[1][c][2 * lane];
            ull v23 = *(const ull*)&sm.u.cmp[1][c][2 * lane + 64];
            ull d0 = d_dup(p0), d1 = d_dup(p1);
            d_fma2(oC[0][0], d0, v01); d_fma2(oC[0][1], d0, v23);
            d_fma2(oC[1][0], d1, v01); d_fma2(oC[1][1], d1, v23);
        }
        *(float2*)&sm.Ocmp[h0][2 * lane] = d_unpack(oC[0][0]);
        *(float2*)&sm.Ocmp[h0][2 * lane + 64] = d_unpack(oC[0][1]);
        *(float2*)&sm.Ocmp[h1][2 * lane] = d_unpack(oC[1][0]);
        *(float2*)&sm.Ocmp[h1][2 * lane + 64] = d_unpack(oC[1][1]);
    }
    __syncthreads();

    int bsS[4], bsW[4];
#pragma unroll
    for (int n = 0; n < TOPN_; n++) bsS[n] = sm.idxs[n] * BLK_;
    const int wstart = (s >= WIN_) ? (s - WIN_ + 1) : 0;
#pragma unroll
    for (int n = 0; n < 4; n++) bsW[n] = wstart + n * BLK_;

    float cS[2][4] = {{0, 0, 0, 0}, {0, 0, 0, 0}};
    float cW[2][4] = {{0, 0, 0, 0}, {0, 0, 0, 0}};
    attn_branch(sm, bsS, s, g, tid, w, lane, sQh, sQl, sKh, sKl, sPh, sPl, cS);
    attn_branch(sm, bsW, s, g, tid, w, lane, sQh, sQl, sKh, sKl, sPh, sPl, cW);

    // ---- gated combine ----
    const int qrow = lane >> 2, qcol = lane & 3;
#pragma unroll
    for (int rr = 0; rr < 2; rr++) {
        const int h = qrow + 8 * rr;
        const float* gp = &g_gates[(size_t)(s * H_ + g * HG_ + h) * 3];
        float g0 = gp[0], g1 = gp[1], g2 = gp[2];
        float* op = &g_ocomb[(size_t)(s * H_ + g * HG_ + h) * DV_];
#pragma unroll
        for (int nt = 0; nt < 2; nt++) {
            const int col = w * 16 + nt * 8 + 2 * qcol;
            float2 o;
            o.x = g0 * sm.Ocmp[h][col] + g1 * cS[nt][rr * 2] + g2 * cW[nt][rr * 2];
            o.y = g0 * sm.Ocmp[h][col + 1] + g1 * cS[nt][rr * 2 + 1] +
                  g2 * cW[nt][rr * 2 + 1];
            *(float2*)&op[col] = o;
        }
    }
}

// ---------------------------------------------------------------------------
extern "C" void kernel_launch(void* const* d_in, const int* in_sizes, int n_in,
                              void* d_out, int out_size) {
    const float* x    = (const float*)d_in[0];
    const float* cosp = (const float*)d_in[1];
    const float* sinp = (const float*)d_in[2];
    const float* Wq   = (const float*)d_in[3];
    const float* Wk   = (const float*)d_in[4];
    const float* Wv   = (const float*)d_in[5];
    const float* Wo   = (const float*)d_in[6];
    const float* Wc   = (const float*)d_in[7];
    float* out = (float*)d_out;

    float *p_qraw, *p_kraw, *p_v, *p_gates;
    cudaGetSymbolAddress((void**)&p_qraw, g_qraw);
    cudaGetSymbolAddress((void**)&p_kraw, g_kraw);
    cudaGetSymbolAddress((void**)&p_v, g_v);
    cudaGetSymbolAddress((void**)&p_gates, g_gates);

    cudaFuncSetAttribute(fused_proj_mma,
                         cudaFuncAttributeMaxDynamicSharedMemorySize, GEMM_SMEM);
    cudaFuncSetAttribute(gemm_out_mma,
                         cudaFuncAttributeMaxDynamicSharedMemorySize, GEMM_SMEM);
    cudaFuncSetAttribute(attn_fused_kernel,
                         cudaFuncAttributeMaxDynamicSharedMemorySize, sizeof(AttnSmem));

    // 1: split conversions
    cvt_all_kernel<<<(5029888 + 255) / 256, 256>>>(x, Wq, Wk, Wv, Wc, Wo);

    // 2: fused projections (tensor cores)
    fused_proj_mma<<<dim3(37, 8), 256, GEMM_SMEM>>>(p_qraw, p_kraw, p_v, p_gates);

    // 3: rope+split q/k, v split, sigmoid, block means
    const int ew_total = S_ * NQ_ + 2 * S_ * NKV_ + S_ * NC_ + C_ * G_ * DQ_;
    ew_all_kernel<<<(ew_total + 255) / 256, 256>>>(cosp, sinp);

    // 4: fused attention (tensor-core QK/PV) — ncu capture slot
    attn_fused_kernel<<<dim3(S_, G_), 256, sizeof(AttnSmem)>>>();

    // 5: split ocomb; 6: output projection
    cvt_ocomb_kernel<<<(S_ * H_ * DV_ / 4 + 255) / 256, 256>>>();
    gemm_out_mma<<<dim3(16, 8), 256, GEMM_SMEM>>>(out);
}